// round 2
// baseline (speedup 1.0000x reference)
#include <cuda_runtime.h>

#define BATCH 512
#define NPTS  512
#define NROT  12
#define IMG   64

// ---------------- scratch (device globals; no allocations allowed) ----------
__device__ unsigned int g_keys[BATCH * NROT * IMG * IMG];        // ~100.7 MB
__device__ float g_c1[BATCH * 32 * 31 * 31];                     // 63 MB
__device__ float g_c2[BATCH * 64 * 15 * 15];                     // 29.5 MB
__device__ float g_feat[BATCH * 6272];                           // 12.8 MB
__device__ float g_h1c[BATCH * 256], g_h1r[BATCH * 256];
__device__ float g_h2c[BATCH * 256], g_h2r[BATCH * 256];
__device__ float g_partC[4 * BATCH * 256], g_partR[4 * BATCH * 256];
__device__ float g_wt1[108 * 32];
__device__ float g_wt2[2 * 288 * 32];
__device__ float g_wt3[2 * 576 * 64];

// ---------------- zero key array -------------------------------------------
__global__ void k_zero(void) {
    size_t i = (size_t)blockIdx.x * blockDim.x + threadIdx.x;
    ((uint4*)g_keys)[i] = make_uint4(0u, 0u, 0u, 0u);
}

// ---------------- scatter: points -> packed (n, value) keys ----------------
// key = (n << 23) | (float_bits >> 9).  atomicMax => largest point index wins
// (replicates JAX scatter-set "last write wins"), value keeps 14 mantissa bits.
__global__ void k_scatter(const float* __restrict__ pts,
                          const float* __restrict__ rot) {
    int bm = blockIdx.x;               // b * NROT + m
    int m  = bm % NROT;
    int b  = bm / NROT;
    int n  = threadIdx.x;              // 512 points
    const float* r = rot + m * 9;
    float r00 = r[0], r01 = r[1], r02 = r[2];
    float r20 = r[6], r21 = r[7], r22 = r[8];
    const float* p = pts + ((size_t)b * NPTS + n) * 3;
    float x = p[0], y = p[1], z = p[2];
    float xr = r00 * x + r01 * y + r02 * z;
    float yr = y;                           // rotation row 1 = [0,1,0]
    float zr = r20 * x + r21 * y + r22 * z;
    float fx = rintf((xr + 2.0f) / 0.0625f);   // round-half-even == jnp.round
    float fy = rintf((yr + 2.0f) / 0.0625f);
    int px = (int)fx, py = (int)fy;
    bool ok = (px >= 0) && (px < IMG) && (py >= 0) && (py < IMG);
    if (!ok) { px = 0; py = 0; }               // proj *= ok : OOB writes (0,0)
    float val = zr / 10.0f;
    unsigned int key = ((unsigned int)n << 23) | (__float_as_uint(val) >> 9);
    atomicMax(&g_keys[((size_t)bm * IMG + py) * IMG + px], key);
}

// ---------------- weight transpose: (OC,R) -> (R,OC) contiguous ------------
__global__ void k_transw(const float* __restrict__ src, float* __restrict__ dst,
                         int OC, int R, int ocOff) {
    int i = blockIdx.x * 256 + threadIdx.x;
    if (i >= OC * R) return;
    int r = i / OC, oc = i % OC;
    dst[i] = src[(size_t)(ocOff + oc) * R + r];
}

// ---------------- conv1: 12ch 64x64 -> 32ch 31x31, stride2, leaky ----------
__global__ void k_conv1(const float* __restrict__ bias) {
    __shared__ float s_in[NROT * 3 * 64];   // 9216 B
    __shared__ float s_w[108 * 32];         // 13824 B
    int blk = blockIdx.x;
    int b = blk / 31, oy = blk % 31;
    int t = threadIdx.x;                    // 128
    for (int i = t; i < 108 * 32 / 4; i += 128)
        ((float4*)s_w)[i] = ((const float4*)g_wt1)[i];
    const unsigned int* keys = g_keys + (size_t)b * (NROT * IMG * IMG);
    for (int i = t; i < NROT * 3 * 64; i += 128) {
        int ic = i / 192, rem = i % 192;
        int ky = rem >> 6, x = rem & 63;
        unsigned int k = keys[(ic * IMG + 2 * oy + ky) * IMG + x];
        s_in[i] = __uint_as_float((k & 0x7fffffu) << 9);   // decode value
    }
    __syncthreads();
    int ox = t & 31, ocg = t >> 5;          // 4 groups of 8 oc
    if (ox >= 31) return;
    float acc[8];
#pragma unroll
    for (int i = 0; i < 8; i++) acc[i] = bias[ocg * 8 + i];
#pragma unroll
    for (int ic = 0; ic < NROT; ic++) {
#pragma unroll
        for (int ky = 0; ky < 3; ky++) {
#pragma unroll
            for (int kx = 0; kx < 3; kx++) {
                float v = s_in[(ic * 3 + ky) * 64 + 2 * ox + kx];
                const float4* wp =
                    (const float4*)&s_w[(ic * 9 + ky * 3 + kx) * 32 + ocg * 8];
                float4 w0 = wp[0], w1 = wp[1];
                acc[0] += v * w0.x; acc[1] += v * w0.y;
                acc[2] += v * w0.z; acc[3] += v * w0.w;
                acc[4] += v * w1.x; acc[5] += v * w1.y;
                acc[6] += v * w1.z; acc[7] += v * w1.w;
            }
        }
    }
    float* o = g_c1 + (size_t)b * 32 * 961;
#pragma unroll
    for (int i = 0; i < 8; i++) {
        float yv = acc[i];
        yv = yv >= 0.f ? yv : 0.2f * yv;
        o[(ocg * 8 + i) * 961 + oy * 31 + ox] = yv;
    }
}

// ---------------- conv2: 32ch 31x31 -> 64ch 15x15 (oc halves) --------------
__global__ void k_conv2(const float* __restrict__ bias) {
    __shared__ float s_in[32 * 3 * 31];     // 11904 B
    __shared__ float s_w[288 * 32];         // 36864 B
    int blk = blockIdx.x;
    int b = blk / 15, oy = blk % 15;
    int och = blockIdx.y;                   // 0/1: 32 oc each
    int t = threadIdx.x;                    // 64
    const float4* wsrc = (const float4*)(g_wt2 + och * 288 * 32);
    for (int i = t; i < 288 * 32 / 4; i += 64) ((float4*)s_w)[i] = wsrc[i];
    const float* in = g_c1 + (size_t)b * 32 * 961;
    for (int i = t; i < 32 * 3 * 31; i += 64) {
        int ic = i / 93, rem = i % 93;
        int ky = rem / 31, x = rem % 31;
        s_in[i] = in[ic * 961 + (2 * oy + ky) * 31 + x];
    }
    __syncthreads();
    int ox = t & 15, ocg = t >> 4;          // 4 groups of 8 oc
    if (ox >= 15) return;
    float acc[8];
#pragma unroll
    for (int i = 0; i < 8; i++) acc[i] = bias[och * 32 + ocg * 8 + i];
    for (int ic = 0; ic < 32; ic++) {
#pragma unroll
        for (int ky = 0; ky < 3; ky++) {
#pragma unroll
            for (int kx = 0; kx < 3; kx++) {
                float v = s_in[(ic * 3 + ky) * 31 + 2 * ox + kx];
                const float4* wp =
                    (const float4*)&s_w[(ic * 9 + ky * 3 + kx) * 32 + ocg * 8];
                float4 w0 = wp[0], w1 = wp[1];
                acc[0] += v * w0.x; acc[1] += v * w0.y;
                acc[2] += v * w0.z; acc[3] += v * w0.w;
                acc[4] += v * w1.x; acc[5] += v * w1.y;
                acc[6] += v * w1.z; acc[7] += v * w1.w;
            }
        }
    }
#pragma unroll
    for (int i = 0; i < 8; i++) {
        float yv = acc[i];
        yv = yv >= 0.f ? yv : 0.2f * yv;
        int oc = och * 32 + ocg * 8 + i;
        g_c2[((size_t)b * 64 + oc) * 225 + oy * 15 + ox] = yv;
    }
}

// ---------------- conv3: 64ch 15x15 -> 128ch 7x7 -> feat -------------------
__global__ void k_conv3(const float* __restrict__ bias) {
    extern __shared__ float sm[];
    float* s_w = sm;                 // 576*64 floats
    float* s_in = sm + 576 * 64;     // 64*225 floats
    int b = blockIdx.x;
    int och = blockIdx.y;            // 0/1: 64 oc each
    int t = threadIdx.x;             // 256
    const float4* wsrc = (const float4*)(g_wt3 + och * 576 * 64);
    for (int i = t; i < 576 * 64 / 4; i += 256) ((float4*)s_w)[i] = wsrc[i];
    const float* in = g_c2 + (size_t)b * 64 * 225;
    for (int i = t; i < 64 * 225; i += 256) s_in[i] = in[i];
    __syncthreads();
    int sp = t & 63, ocg = t >> 6;   // 4 groups of 16 oc
    if (sp >= 49) return;
    int oyy = sp / 7, oxx = sp % 7;
    float acc[16];
#pragma unroll
    for (int i = 0; i < 16; i++) acc[i] = bias[och * 64 + ocg * 16 + i];
    for (int ic = 0; ic < 64; ic++) {
#pragma unroll
        for (int ky = 0; ky < 3; ky++) {
#pragma unroll
            for (int kx = 0; kx < 3; kx++) {
                float v = s_in[ic * 225 + (2 * oyy + ky) * 15 + 2 * oxx + kx];
                const float4* wp =
                    (const float4*)&s_w[(ic * 9 + ky * 3 + kx) * 64 + ocg * 16];
                float4 w0 = wp[0], w1 = wp[1], w2 = wp[2], w3 = wp[3];
                acc[0]  += v * w0.x; acc[1]  += v * w0.y;
                acc[2]  += v * w0.z; acc[3]  += v * w0.w;
                acc[4]  += v * w1.x; acc[5]  += v * w1.y;
                acc[6]  += v * w1.z; acc[7]  += v * w1.w;
                acc[8]  += v * w2.x; acc[9]  += v * w2.y;
                acc[10] += v * w2.z; acc[11] += v * w2.w;
                acc[12] += v * w3.x; acc[13] += v * w3.y;
                acc[14] += v * w3.z; acc[15] += v * w3.w;
            }
        }
    }
    float* o = g_feat + (size_t)b * 6272;
#pragma unroll
    for (int i = 0; i < 16; i++) {
        float yv = acc[i];
        yv = yv >= 0.f ? yv : 0.2f * yv;
        int oc = och * 64 + ocg * 16 + i;
        o[oc * 49 + oyy * 7 + oxx] = yv;      // matches reshape(B,-1)
    }
}

// ---------------- GEMM: C[512,256] = A[512,K] * W[256,K]^T (split-K) -------
__global__ void k_gemm(const float* __restrict__ A, const float* __restrict__ Bw,
                       float* __restrict__ part, int K, int Ksplit) {
    __shared__ float sA[16 * 64];
    __shared__ float sB[16 * 64];
    int m0 = blockIdx.x * 64, n0 = blockIdx.y * 64;
    int k0 = blockIdx.z * Ksplit;
    int t = threadIdx.x;                 // 256
    int lrow = t >> 2, lkq = (t & 3) << 2;
    const float* Ap = A + (size_t)(m0 + lrow) * K + k0 + lkq;
    const float* Bp = Bw + (size_t)(n0 + lrow) * K + k0 + lkq;
    int tm = t >> 4, tn = t & 15;
    float acc[16];
#pragma unroll
    for (int i = 0; i < 16; i++) acc[i] = 0.f;
    for (int kk = 0; kk < Ksplit; kk += 16) {
        float4 av = *(const float4*)(Ap + kk);
        float4 bv = *(const float4*)(Bp + kk);
        __syncthreads();
        sA[(lkq + 0) * 64 + lrow] = av.x; sA[(lkq + 1) * 64 + lrow] = av.y;
        sA[(lkq + 2) * 64 + lrow] = av.z; sA[(lkq + 3) * 64 + lrow] = av.w;
        sB[(lkq + 0) * 64 + lrow] = bv.x; sB[(lkq + 1) * 64 + lrow] = bv.y;
        sB[(lkq + 2) * 64 + lrow] = bv.z; sB[(lkq + 3) * 64 + lrow] = bv.w;
        __syncthreads();
#pragma unroll
        for (int k = 0; k < 16; k++) {
            float4 a = *(const float4*)&sA[k * 64 + tm * 4];
            float4 bq = *(const float4*)&sB[k * 64 + tn * 4];
            acc[0]  += a.x * bq.x; acc[1]  += a.x * bq.y;
            acc[2]  += a.x * bq.z; acc[3]  += a.x * bq.w;
            acc[4]  += a.y * bq.x; acc[5]  += a.y * bq.y;
            acc[6]  += a.y * bq.z; acc[7]  += a.y * bq.w;
            acc[8]  += a.z * bq.x; acc[9]  += a.z * bq.y;
            acc[10] += a.z * bq.z; acc[11] += a.z * bq.w;
            acc[12] += a.w * bq.x; acc[13] += a.w * bq.y;
            acc[14] += a.w * bq.z; acc[15] += a.w * bq.w;
        }
    }
    float* p = part + (size_t)blockIdx.z * (512 * 256);
#pragma unroll
    for (int i = 0; i < 4; i++)
#pragma unroll
        for (int j = 0; j < 4; j++)
            p[(m0 + tm * 4 + i) * 256 + n0 + tn * 4 + j] = acc[i * 4 + j];
}

// ---------------- split-K reduce + bias + relu -----------------------------
__global__ void k_reduce(const float* __restrict__ part,
                         const float* __restrict__ bias,
                         float* __restrict__ out, int S, int act) {
    int i = blockIdx.x * 256 + threadIdx.x;     // MN = 512*256
    float v = 0.f;
    for (int s = 0; s < S; s++) v += part[(size_t)s * (512 * 256) + i];
    v += bias[i & 255];
    if (act) v = fmaxf(v, 0.f);
    out[i] = v;
}

// ---------------- final heads ----------------------------------------------
__global__ void k_fc3(const float* __restrict__ cw, const float* __restrict__ cb,
                      const float* __restrict__ rw, const float* __restrict__ rb,
                      float* __restrict__ out) {
    __shared__ float hc[256], hr[256];
    int b = blockIdx.x, t = threadIdx.x;        // 64
    for (int i = t; i < 256; i += 64) {
        hc[i] = g_h2c[b * 256 + i];
        hr[i] = g_h2r[b * 256 + i];
    }
    __syncthreads();
    if (t >= 47) return;
    const float* w = (t == 0) ? cw : rw + (t - 1) * 256;
    const float* h = (t == 0) ? hc : hr;
    float acc = (t == 0) ? cb[0] : rb[t - 1];
    for (int k = 0; k < 256; k++) acc += h[k] * w[k];
    if (t == 0) out[b] = acc;
    else        out[512 + b * 46 + (t - 1)] = acc;
}

// ---------------- launch ----------------------------------------------------
extern "C" void kernel_launch(void* const* d_in, const int* in_sizes, int n_in,
                              void* d_out, int out_size) {
    const float* pts = (const float*)d_in[0];
    const float* rot = (const float*)d_in[1];
    const float* w1  = (const float*)d_in[2];  const float* b1  = (const float*)d_in[3];
    const float* w2  = (const float*)d_in[4];  const float* b2  = (const float*)d_in[5];
    const float* w3  = (const float*)d_in[6];  const float* b3  = (const float*)d_in[7];
    const float* cw1 = (const float*)d_in[8];  const float* cb1 = (const float*)d_in[9];
    const float* cw2 = (const float*)d_in[10]; const float* cb2 = (const float*)d_in[11];
    const float* cw3 = (const float*)d_in[12]; const float* cb3 = (const float*)d_in[13];
    const float* rw1 = (const float*)d_in[14]; const float* rb1 = (const float*)d_in[15];
    const float* rw2 = (const float*)d_in[16]; const float* rb2 = (const float*)d_in[17];
    const float* rw3 = (const float*)d_in[18]; const float* rb3 = (const float*)d_in[19];
    float* out = (float*)d_out;

    float *featp, *h1cp, *h1rp, *h2cp, *h2rp, *partCp, *partRp;
    float *wt1p, *wt2p, *wt3p;
    cudaGetSymbolAddress((void**)&featp, g_feat);
    cudaGetSymbolAddress((void**)&h1cp, g_h1c);
    cudaGetSymbolAddress((void**)&h1rp, g_h1r);
    cudaGetSymbolAddress((void**)&h2cp, g_h2c);
    cudaGetSymbolAddress((void**)&h2rp, g_h2r);
    cudaGetSymbolAddress((void**)&partCp, g_partC);
    cudaGetSymbolAddress((void**)&partRp, g_partR);
    cudaGetSymbolAddress((void**)&wt1p, g_wt1);
    cudaGetSymbolAddress((void**)&wt2p, g_wt2);
    cudaGetSymbolAddress((void**)&wt3p, g_wt3);

    const int CONV3_SMEM = (576 * 64 + 64 * 225) * 4;   // 205056 B
    cudaFuncSetAttribute(k_conv3, cudaFuncAttributeMaxDynamicSharedMemorySize,
                         CONV3_SMEM);

    // 1) reset scatter keys (100.7 MB)
    k_zero<<<24576, 256>>>();
    // 2) pre-transpose conv weights -> [r][oc] contiguous blocks
    k_transw<<<(3456 + 255) / 256, 256>>>(w1, wt1p, 32, 108, 0);
    k_transw<<<36, 256>>>(w2, wt2p,          32, 288, 0);
    k_transw<<<36, 256>>>(w2, wt2p + 9216,   32, 288, 32);
    k_transw<<<144, 256>>>(w3, wt3p,         64, 576, 0);
    k_transw<<<144, 256>>>(w3, wt3p + 36864, 64, 576, 64);
    // 3) scatter points into packed images
    k_scatter<<<BATCH * NROT, NPTS>>>(pts, rot);
    // 4) convs
    k_conv1<<<BATCH * 31, 128>>>(b1);
    k_conv2<<<dim3(BATCH * 15, 2), 64>>>(b2);
    k_conv3<<<dim3(BATCH, 2), 256, CONV3_SMEM>>>(b3);
    // 5) FC1 (split-K = 4), both heads
    k_gemm<<<dim3(8, 4, 4), 256>>>(featp, cw1, partCp, 6272, 1568);
    k_gemm<<<dim3(8, 4, 4), 256>>>(featp, rw1, partRp, 6272, 1568);
    k_reduce<<<512, 256>>>(partCp, cb1, h1cp, 4, 1);
    k_reduce<<<512, 256>>>(partRp, rb1, h1rp, 4, 1);
    // 6) FC2 (split-K = 2)
    k_gemm<<<dim3(8, 4, 2), 256>>>(h1cp, cw2, partCp, 256, 128);
    k_gemm<<<dim3(8, 4, 2), 256>>>(h1rp, rw2, partRp, 256, 128);
    k_reduce<<<512, 256>>>(partCp, cb2, h2cp, 2, 1);
    k_reduce<<<512, 256>>>(partRp, rb2, h2rp, 2, 1);
    // 7) heads -> output
    k_fc3<<<BATCH, 64>>>(cw3, cb3, rw3, rb3, out);
    (void)in_sizes; (void)n_in; (void)out_size;
}

// round 6
// speedup vs baseline: 1.1219x; 1.1219x over previous
#include <cuda_runtime.h>

#define BATCH 512
#define NPTS  512
#define NROT  12
#define IMG   64

// ---------------- scratch (device globals; no allocations allowed) ----------
__device__ float g_c1[BATCH * 32 * 31 * 32];          // deint-x, 65 MB
__device__ float g_c2[BATCH * 64 * 15 * 16];          // deint-x, 31.5 MB
__device__ float g_feat[BATCH * 6272];                // 12.8 MB
__device__ float g_h1[2 * BATCH * 256];
__device__ float g_h2[2 * BATCH * 256];
__device__ float g_part[4 * 2 * BATCH * 256];         // [split][head][b][n]
__device__ float g_wt1[108 * 32];                     // [r][oc]
__device__ float g_wt2[288 * 64];                     // [r][oc]
__device__ float g_wt3[2 * 576 * 64];                 // [half][r][oc]

__device__ __forceinline__ float leaky(float v) {
    return v >= 0.f ? v : 0.2f * v;
}

// ---------------- weight prep: transpose (OC,R) -> (R,OC) -------------------
__global__ void k_prep(const float* __restrict__ w1, const float* __restrict__ w2,
                       const float* __restrict__ w3) {
    int i = blockIdx.x * 256 + threadIdx.x;
    if (i < 3456) {
        int r = i >> 5, oc = i & 31;
        g_wt1[i] = w1[oc * 108 + r];
        return;
    }
    i -= 3456;
    if (i < 18432) {
        int r = i >> 6, oc = i & 63;
        g_wt2[i] = w2[oc * 288 + r];
        return;
    }
    i -= 18432;
    if (i < 73728) {
        int h = i / 36864, j = i % 36864;
        int r = j >> 6, oc = j & 63;
        g_wt3[i] = w3[(h * 64 + oc) * 576 + r];
    }
}

// ---------------- fused scatter + conv1 (per-batch block) -------------------
// smem: image 12x64x64 (x-deinterleaved) + weights + points + rot
__global__ void __launch_bounds__(1024, 1) k_fuse1(
    const float* __restrict__ pts, const float* __restrict__ rot,
    const float* __restrict__ bias) {
    extern __shared__ float sm[];
    float* s_img = sm;                    // 49152 floats
    float* s_w   = sm + 49152;            // 3456
    float* s_pts = s_w + 3456;            // 1536
    float* s_rot = s_pts + 1536;          // 108
    unsigned int* u_img = (unsigned int*)s_img;
    int b = blockIdx.x, t = threadIdx.x;

    for (int i = t; i < 49152 / 4; i += 1024)
        ((uint4*)u_img)[i] = make_uint4(0u, 0u, 0u, 0u);
    for (int i = t; i < 1536; i += 1024) s_pts[i] = pts[b * 1536 + i];
    if (t < 108) s_rot[t] = rot[t];
    for (int i = t; i < 3456 / 4; i += 1024)
        ((float4*)s_w)[i] = ((const float4*)g_wt1)[i];
    __syncthreads();

    // scatter: key = (n<<23) | (valbits>>9); atomicMax => last point index wins
    // (replicates JAX .at[].set last-write-wins; 14 mantissa bits ~ 3e-5 rel)
    for (int task = t; task < NROT * NPTS; task += 1024) {
        int m = task >> 9, n = task & 511;
        float x = s_pts[n * 3], y = s_pts[n * 3 + 1], z = s_pts[n * 3 + 2];
        const float* r = s_rot + m * 9;
        float xr = r[0] * x + r[1] * y + r[2] * z;
        float zr = r[6] * x + r[7] * y + r[8] * z;
        float fx = rintf((xr + 2.0f) / 0.0625f);   // round-half-even == jnp.round
        float fy = rintf((y + 2.0f) / 0.0625f);
        int px = (int)fx, py = (int)fy;
        bool ok = (px >= 0) && (px < IMG) && (py >= 0) && (py < IMG);
        if (!ok) { px = 0; py = 0; }               // proj*ok -> OOB hits (0,0)
        float val = zr / 10.0f;
        unsigned int key = ((unsigned int)n << 23) | (__float_as_uint(val) >> 9);
        int didx = ((px & 1) << 5) + (px >> 1);    // deinterleave x
        atomicMax(&u_img[(m << 12) + (py << 6) + didx], key);
    }
    __syncthreads();
    for (int i = t; i < 49152; i += 1024)
        u_img[i] = (u_img[i] & 0x7fffffu) << 9;    // decode to float bits
    __syncthreads();

    // conv1: 12ch 64x64 -> 32ch 31x31 stride-2 leaky. 16 oc per thread.
    int ocg = t >> 9;                   // 0..1
    int oc0 = ocg << 4;
    float bias_r[16];
#pragma unroll
    for (int i = 0; i < 16; i++) bias_r[i] = bias[oc0 + i];

    for (int pix = t & 511; pix < 961; pix += 512) {
        int oy = pix / 31, ox = pix - oy * 31;
        float acc[16];
#pragma unroll
        for (int i = 0; i < 16; i++) acc[i] = bias_r[i];
        for (int ic = 0; ic < NROT; ic++) {
#pragma unroll
            for (int ky = 0; ky < 3; ky++) {
                const float* row = s_img + (ic << 12) + ((2 * oy + ky) << 6);
                float v0 = row[ox], v1 = row[32 + ox], v2 = row[ox + 1];
#pragma unroll
                for (int kx = 0; kx < 3; kx++) {
                    float v = (kx == 0) ? v0 : (kx == 1 ? v1 : v2);
                    const float4* wp = (const float4*)
                        (s_w + ((ic * 9 + ky * 3 + kx) << 5) + oc0);
                    float4 w0 = wp[0], w1 = wp[1], w2 = wp[2], w3 = wp[3];
                    acc[0]  = fmaf(v, w0.x, acc[0]);  acc[1]  = fmaf(v, w0.y, acc[1]);
                    acc[2]  = fmaf(v, w0.z, acc[2]);  acc[3]  = fmaf(v, w0.w, acc[3]);
                    acc[4]  = fmaf(v, w1.x, acc[4]);  acc[5]  = fmaf(v, w1.y, acc[5]);
                    acc[6]  = fmaf(v, w1.z, acc[6]);  acc[7]  = fmaf(v, w1.w, acc[7]);
                    acc[8]  = fmaf(v, w2.x, acc[8]);  acc[9]  = fmaf(v, w2.y, acc[9]);
                    acc[10] = fmaf(v, w2.z, acc[10]); acc[11] = fmaf(v, w2.w, acc[11]);
                    acc[12] = fmaf(v, w3.x, acc[12]); acc[13] = fmaf(v, w3.y, acc[13]);
                    acc[14] = fmaf(v, w3.z, acc[14]); acc[15] = fmaf(v, w3.w, acc[15]);
                }
            }
        }
        int didx = ((ox & 1) << 4) + (ox >> 1);
        float* o = g_c1 + (((size_t)b * 32 + oc0) * 31 + oy) * 32 + didx;
#pragma unroll
        for (int i = 0; i < 16; i++) o[i * 992] = leaky(acc[i]);
    }
}

// ---------------- conv2: 32ch 31x31 -> 64ch 15x15 (per-batch block) ---------
__global__ void __launch_bounds__(1024, 1) k_conv2(const float* __restrict__ bias) {
    extern __shared__ float sm[];
    float* s_in = sm;                     // 32*31*32 = 31744
    float* s_w  = sm + 31744;             // 288*64 = 18432
    int b = blockIdx.x, t = threadIdx.x;
    const float4* in4 = (const float4*)(g_c1 + (size_t)b * 31744);
    for (int i = t; i < 31744 / 4; i += 1024) ((float4*)s_in)[i] = in4[i];
    for (int i = t; i < 18432 / 4; i += 1024)
        ((float4*)s_w)[i] = ((const float4*)g_wt2)[i];
    __syncthreads();

    int ocg = t >> 8;                     // 4 groups of 16 oc
    int oc0 = ocg << 4;
    int pix = t & 255;
    if (pix >= 225) return;
    int oy = pix / 15, ox = pix - oy * 15;
    float acc[16];
#pragma unroll
    for (int i = 0; i < 16; i++) acc[i] = bias[oc0 + i];
    for (int ic = 0; ic < 32; ic++) {
#pragma unroll
        for (int ky = 0; ky < 3; ky++) {
            const float* row = s_in + ic * 992 + (2 * oy + ky) * 32;
            float v0 = row[ox], v1 = row[16 + ox], v2 = row[ox + 1];
#pragma unroll
            for (int kx = 0; kx < 3; kx++) {
                float v = (kx == 0) ? v0 : (kx == 1 ? v1 : v2);
                const float4* wp = (const float4*)
                    (s_w + ((ic * 9 + ky * 3 + kx) << 6) + oc0);
                float4 w0 = wp[0], w1 = wp[1], w2 = wp[2], w3 = wp[3];
                acc[0]  = fmaf(v, w0.x, acc[0]);  acc[1]  = fmaf(v, w0.y, acc[1]);
                acc[2]  = fmaf(v, w0.z, acc[2]);  acc[3]  = fmaf(v, w0.w, acc[3]);
                acc[4]  = fmaf(v, w1.x, acc[4]);  acc[5]  = fmaf(v, w1.y, acc[5]);
                acc[6]  = fmaf(v, w1.z, acc[6]);  acc[7]  = fmaf(v, w1.w, acc[7]);
                acc[8]  = fmaf(v, w2.x, acc[8]);  acc[9]  = fmaf(v, w2.y, acc[9]);
                acc[10] = fmaf(v, w2.z, acc[10]); acc[11] = fmaf(v, w2.w, acc[11]);
                acc[12] = fmaf(v, w3.x, acc[12]); acc[13] = fmaf(v, w3.y, acc[13]);
                acc[14] = fmaf(v, w3.z, acc[14]); acc[15] = fmaf(v, w3.w, acc[15]);
            }
        }
    }
    int didx = ((ox & 1) << 3) + (ox >> 1);
    float* o = g_c2 + (((size_t)b * 64 + oc0) * 15 + oy) * 16 + didx;
#pragma unroll
    for (int i = 0; i < 16; i++) o[i * 240] = leaky(acc[i]);
}

// ---------------- conv3: 64ch 15x15 -> 128ch 7x7 -> feat --------------------
__global__ void __launch_bounds__(512, 1) k_conv3(const float* __restrict__ bias) {
    extern __shared__ float sm[];
    float* s_in = sm;                     // 64*15*16 = 15360
    float* s_w  = sm + 15360;             // 576*64 = 36864
    int b = blockIdx.x, och = blockIdx.y, t = threadIdx.x;
    const float4* in4 = (const float4*)(g_c2 + (size_t)b * 15360);
    for (int i = t; i < 15360 / 4; i += 512) ((float4*)s_in)[i] = in4[i];
    const float4* w4 = (const float4*)(g_wt3 + och * 36864);
    for (int i = t; i < 36864 / 4; i += 512) ((float4*)s_w)[i] = w4[i];
    __syncthreads();

    int ocg = t & 7;                      // 8 groups of 8 oc
    int px = t >> 3;
    if (px >= 49) return;
    int oyy = px / 7, oxx = px - oyy * 7;
    int ocl = ocg << 3;                   // local oc within half
    int oc0 = och * 64 + ocl;
    float acc[8];
#pragma unroll
    for (int i = 0; i < 8; i++) acc[i] = bias[oc0 + i];
    for (int ic = 0; ic < 64; ic++) {
#pragma unroll
        for (int ky = 0; ky < 3; ky++) {
            const float* row = s_in + ic * 240 + (2 * oyy + ky) * 16;
            float v0 = row[oxx], v1 = row[8 + oxx], v2 = row[oxx + 1];
#pragma unroll
            for (int kx = 0; kx < 3; kx++) {
                float v = (kx == 0) ? v0 : (kx == 1 ? v1 : v2);
                const float4* wp = (const float4*)
                    (s_w + ((ic * 9 + ky * 3 + kx) << 6) + ocl);
                float4 w0 = wp[0], w1 = wp[1];
                acc[0] = fmaf(v, w0.x, acc[0]); acc[1] = fmaf(v, w0.y, acc[1]);
                acc[2] = fmaf(v, w0.z, acc[2]); acc[3] = fmaf(v, w0.w, acc[3]);
                acc[4] = fmaf(v, w1.x, acc[4]); acc[5] = fmaf(v, w1.y, acc[5]);
                acc[6] = fmaf(v, w1.z, acc[6]); acc[7] = fmaf(v, w1.w, acc[7]);
            }
        }
    }
    float* o = g_feat + (size_t)b * 6272 + oc0 * 49 + oyy * 7 + oxx;
#pragma unroll
    for (int i = 0; i < 8; i++) o[i * 49] = leaky(acc[i]);
}

// ---------------- fused dual-head GEMM (split-K) ----------------------------
// C[head][512,256] = A[head] * W[head]^T ; blockIdx.y: [0..3]=cls n-tile, [4..7]=reg
__global__ void k_gemm(const float* __restrict__ Ac, const float* __restrict__ Ar,
                       const float* __restrict__ Bc, const float* __restrict__ Br,
                       float* __restrict__ part, int K, int Ksplit) {
    __shared__ float sA[16 * 64];
    __shared__ float sB[16 * 64];
    int head = blockIdx.y >> 2;
    int m0 = blockIdx.x * 64, n0 = (blockIdx.y & 3) * 64;
    int k0 = blockIdx.z * Ksplit;
    const float* A  = head ? Ar : Ac;
    const float* Bw = head ? Br : Bc;
    int t = threadIdx.x;                 // 256
    int lrow = t >> 2, lk = (t & 3) << 2;
    const float* Ap = A + (size_t)(m0 + lrow) * K + k0 + lk;
    const float* Bp = Bw + (size_t)(n0 + lrow) * K + k0 + lk;
    int tm = t >> 4, tn = t & 15;
    float acc[16];
#pragma unroll
    for (int i = 0; i < 16; i++) acc[i] = 0.f;
    for (int kk = 0; kk < Ksplit; kk += 16) {
        float4 av = *(const float4*)(Ap + kk);
        float4 bv = *(const float4*)(Bp + kk);
        __syncthreads();
        sA[(lk + 0) * 64 + lrow] = av.x; sA[(lk + 1) * 64 + lrow] = av.y;
        sA[(lk + 2) * 64 + lrow] = av.z; sA[(lk + 3) * 64 + lrow] = av.w;
        sB[(lk + 0) * 64 + lrow] = bv.x; sB[(lk + 1) * 64 + lrow] = bv.y;
        sB[(lk + 2) * 64 + lrow] = bv.z; sB[(lk + 3) * 64 + lrow] = bv.w;
        __syncthreads();
#pragma unroll
        for (int k = 0; k < 16; k++) {
            float4 a = *(const float4*)&sA[k * 64 + tm * 4];
            float4 bq = *(const float4*)&sB[k * 64 + tn * 4];
            acc[0]  = fmaf(a.x, bq.x, acc[0]);  acc[1]  = fmaf(a.x, bq.y, acc[1]);
            acc[2]  = fmaf(a.x, bq.z, acc[2]);  acc[3]  = fmaf(a.x, bq.w, acc[3]);
            acc[4]  = fmaf(a.y, bq.x, acc[4]);  acc[5]  = fmaf(a.y, bq.y, acc[5]);
            acc[6]  = fmaf(a.y, bq.z, acc[6]);  acc[7]  = fmaf(a.y, bq.w, acc[7]);
            acc[8]  = fmaf(a.z, bq.x, acc[8]);  acc[9]  = fmaf(a.z, bq.y, acc[9]);
            acc[10] = fmaf(a.z, bq.z, acc[10]); acc[11] = fmaf(a.z, bq.w, acc[11]);
            acc[12] = fmaf(a.w, bq.x, acc[12]); acc[13] = fmaf(a.w, bq.y, acc[13]);
            acc[14] = fmaf(a.w, bq.z, acc[14]); acc[15] = fmaf(a.w, bq.w, acc[15]);
        }
    }
    float* p = part + (size_t)(blockIdx.z * 2 + head) * (512 * 256);
#pragma unroll
    for (int m = 0; m < 4; m++) {
        float4* row = (float4*)(p + (size_t)(m0 + tm * 4 + m) * 256 + n0 + tn * 4);
        *row = make_float4(acc[m * 4], acc[m * 4 + 1], acc[m * 4 + 2], acc[m * 4 + 3]);
    }
}

// ---------------- split-K reduce + bias + relu (both heads) -----------------
__global__ void k_reduce(const float* __restrict__ part,
                         const float* __restrict__ cb, const float* __restrict__ rb,
                         float* __restrict__ out, int S) {
    int i = blockIdx.x * 256 + threadIdx.x;        // over 2*512*256
    int head = i >> 17;
    int j = i & 131071;
    float v = 0.f;
    for (int s = 0; s < S; s++) v += part[(size_t)(s * 2 + head) * 131072 + j];
    v += (head ? rb : cb)[j & 255];
    out[i] = fmaxf(v, 0.f);
}

// ---------------- final heads ----------------------------------------------
__global__ void k_fc3(const float* __restrict__ cw, const float* __restrict__ cb,
                      const float* __restrict__ rw, const float* __restrict__ rb,
                      float* __restrict__ out) {
    __shared__ float hc[256], hr[256];
    int b = blockIdx.x, t = threadIdx.x;           // 64 threads
    for (int i = t; i < 256; i += 64) {
        hc[i] = g_h2[b * 256 + i];
        hr[i] = g_h2[131072 + b * 256 + i];
    }
    __syncthreads();
    if (t >= 47) return;
    const float* w = (t == 0) ? cw : rw + (t - 1) * 256;
    const float* h = (t == 0) ? hc : hr;
    float acc = (t == 0) ? cb[0] : rb[t - 1];
    for (int k = 0; k < 256; k++) acc = fmaf(h[k], w[k], acc);
    if (t == 0) out[b] = acc;
    else        out[512 + b * 46 + (t - 1)] = acc;
}

// ---------------- launch ----------------------------------------------------
extern "C" void kernel_launch(void* const* d_in, const int* in_sizes, int n_in,
                              void* d_out, int out_size) {
    const float* pts = (const float*)d_in[0];
    const float* rot = (const float*)d_in[1];
    const float* w1  = (const float*)d_in[2];  const float* b1  = (const float*)d_in[3];
    const float* w2  = (const float*)d_in[4];  const float* b2  = (const float*)d_in[5];
    const float* w3  = (const float*)d_in[6];  const float* b3  = (const float*)d_in[7];
    const float* cw1 = (const float*)d_in[8];  const float* cb1 = (const float*)d_in[9];
    const float* cw2 = (const float*)d_in[10]; const float* cb2 = (const float*)d_in[11];
    const float* cw3 = (const float*)d_in[12]; const float* cb3 = (const float*)d_in[13];
    const float* rw1 = (const float*)d_in[14]; const float* rb1 = (const float*)d_in[15];
    const float* rw2 = (const float*)d_in[16]; const float* rb2 = (const float*)d_in[17];
    const float* rw3 = (const float*)d_in[18]; const float* rb3 = (const float*)d_in[19];
    float* out = (float*)d_out;

    float *featp, *h1p, *h2p, *partp;
    cudaGetSymbolAddress((void**)&featp, g_feat);
    cudaGetSymbolAddress((void**)&h1p, g_h1);
    cudaGetSymbolAddress((void**)&h2p, g_h2);
    cudaGetSymbolAddress((void**)&partp, g_part);

    const int SM1 = (49152 + 3456 + 1536 + 128) * 4;   // 217,088 B
    const int SM2 = (31744 + 18432) * 4;               // 200,704 B
    const int SM3 = (15360 + 36864) * 4;               // 208,896 B
    cudaFuncSetAttribute(k_fuse1, cudaFuncAttributeMaxDynamicSharedMemorySize, SM1);
    cudaFuncSetAttribute(k_conv2, cudaFuncAttributeMaxDynamicSharedMemorySize, SM2);
    cudaFuncSetAttribute(k_conv3, cudaFuncAttributeMaxDynamicSharedMemorySize, SM3);

    k_prep<<<(3456 + 18432 + 73728 + 255) / 256, 256>>>(w1, w2, w3);
    k_fuse1<<<BATCH, 1024, SM1>>>(pts, rot, b1);
    k_conv2<<<BATCH, 1024, SM2>>>(b2);
    k_conv3<<<dim3(BATCH, 2), 512, SM3>>>(b3);
    k_gemm<<<dim3(8, 8, 4), 256>>>(featp, featp, cw1, rw1, partp, 6272, 1568);
    k_reduce<<<1024, 256>>>(partp, cb1, rb1, h1p, 4);
    k_gemm<<<dim3(8, 8, 2), 256>>>(h1p, h1p + 131072, cw2, rw2, partp, 256, 128);
    k_reduce<<<1024, 256>>>(partp, cb2, rb2, h2p, 2);
    k_fc3<<<BATCH, 64>>>(cw3, cb3, rw3, rb3, out);
    (void)in_sizes; (void)n_in; (void)out_size;
}

// round 7
// speedup vs baseline: 1.8489x; 1.6479x over previous
#include <cuda_runtime.h>

#define BATCH 512
#define NPTS  512
#define NROT  12
#define IMG   64

// ---------------- scratch (device globals; no allocations allowed) ----------
__device__ float g_c1[BATCH * 32 * 31 * 32];          // deint-x, 65 MB
__device__ float g_c2[BATCH * 64 * 15 * 16];          // deint-x, 31.5 MB
__device__ float g_feat[BATCH * 6272];                // 12.8 MB
__device__ float g_h1[2 * BATCH * 256];
__device__ float g_h2[2 * BATCH * 256];
__device__ float g_part[4 * 2 * BATCH * 256];         // [split*2+head][b][n]
__device__ float g_wt1[108 * 32];                     // [r][oc]
__device__ float g_wt2[288 * 64];                     // [r][oc]
__device__ float g_wt3[576 * 128];                    // [r][oc] (merged halves)

__device__ __forceinline__ float leaky(float v) {
    return v >= 0.f ? v : 0.2f * v;
}

// 8 oc x 4 px outer-product FMA block
__device__ __forceinline__ void fma8x4(float* acc, float v0, float v1,
                                       float v2, float v3,
                                       float4 w0, float4 w1) {
    float w[8] = {w0.x, w0.y, w0.z, w0.w, w1.x, w1.y, w1.z, w1.w};
#pragma unroll
    for (int j = 0; j < 8; j++) {
        acc[j * 4 + 0] = fmaf(v0, w[j], acc[j * 4 + 0]);
        acc[j * 4 + 1] = fmaf(v1, w[j], acc[j * 4 + 1]);
        acc[j * 4 + 2] = fmaf(v2, w[j], acc[j * 4 + 2]);
        acc[j * 4 + 3] = fmaf(v3, w[j], acc[j * 4 + 3]);
    }
}

// ---------------- weight prep: transpose (OC,R) -> (R,OC) -------------------
__global__ void k_prep(const float* __restrict__ w1, const float* __restrict__ w2,
                       const float* __restrict__ w3) {
    int i = blockIdx.x * 256 + threadIdx.x;
    if (i < 3456) {
        int r = i >> 5, oc = i & 31;
        g_wt1[i] = w1[oc * 108 + r];
        return;
    }
    i -= 3456;
    if (i < 18432) {
        int r = i >> 6, oc = i & 63;
        g_wt2[i] = w2[oc * 288 + r];
        return;
    }
    i -= 18432;
    if (i < 73728) {
        int r = i >> 7, oc = i & 127;
        g_wt3[i] = w3[oc * 576 + r];
    }
}

// ---------------- fused scatter + conv1 (per-batch block) -------------------
__global__ void __launch_bounds__(512, 1) k_fuse1(
    const float* __restrict__ pts, const float* __restrict__ rot,
    const float* __restrict__ bias) {
    extern __shared__ float sm[];
    float* s_img = sm;                    // 49152 floats (12 x 64 x 64 deint-x)
    float* s_w   = sm + 49152;            // 3456
    float* s_pts = s_w + 3456;            // 1536
    float* s_rot = s_pts + 1536;          // 108
    unsigned int* u_img = (unsigned int*)s_img;
    int b = blockIdx.x, t = threadIdx.x;

    for (int i = t; i < 49152 / 4; i += 512)
        ((uint4*)u_img)[i] = make_uint4(0u, 0u, 0u, 0u);
    for (int i = t; i < 1536; i += 512) s_pts[i] = pts[b * 1536 + i];
    if (t < 108) s_rot[t] = rot[t];
    for (int i = t; i < 3456 / 4; i += 512)
        ((float4*)s_w)[i] = ((const float4*)g_wt1)[i];
    __syncthreads();

    // scatter: key = (n<<23) | (valbits>>9); atomicMax => last point index wins
    for (int task = t; task < NROT * NPTS; task += 512) {
        int m = task >> 9, n = task & 511;
        float x = s_pts[n * 3], y = s_pts[n * 3 + 1], z = s_pts[n * 3 + 2];
        const float* r = s_rot + m * 9;
        float xr = r[0] * x + r[1] * y + r[2] * z;
        float zr = r[6] * x + r[7] * y + r[8] * z;
        float fx = rintf((xr + 2.0f) / 0.0625f);   // round-half-even == jnp.round
        float fy = rintf((y + 2.0f) / 0.0625f);
        int px = (int)fx, py = (int)fy;
        bool ok = (px >= 0) && (px < IMG) && (py >= 0) && (py < IMG);
        if (!ok) { px = 0; py = 0; }               // proj*ok -> OOB hits (0,0)
        float val = zr / 10.0f;
        unsigned int key = ((unsigned int)n << 23) | (__float_as_uint(val) >> 9);
        int didx = ((px & 1) << 5) + (px >> 1);    // deinterleave x
        atomicMax(&u_img[(m << 12) + (py << 6) + didx], key);
    }
    __syncthreads();
    for (int i = t; i < 49152 / 4; i += 512) {
        uint4 v = ((uint4*)u_img)[i];
        v.x = (v.x & 0x7fffffu) << 9; v.y = (v.y & 0x7fffffu) << 9;
        v.z = (v.z & 0x7fffffu) << 9; v.w = (v.w & 0x7fffffu) << 9;
        ((uint4*)u_img)[i] = v;                    // decode to float bits
    }
    __syncthreads();

    // conv1: 12ch 64x64 -> 32ch 31x31 stride-2 leaky.
    // unit = (ocg of 8 oc) x (pixel quad). 4 ocg x 248 quads; 2 units/thread.
    int pxg = t & 255;
    int row = pxg >> 3, q = pxg & 7;
    bool active = pxg < 248;                        // 31 rows x 8 quads
#pragma unroll
    for (int uu = 0; uu < 2; uu++) {
        int ocg = (t >> 8) + 2 * uu;                // 0..3
        int oc0 = ocg << 3;
        if (active) {
            float acc[32];
#pragma unroll
            for (int j = 0; j < 8; j++) {
                float bv = __ldg(&bias[oc0 + j]);
                acc[j * 4] = bv; acc[j * 4 + 1] = bv;
                acc[j * 4 + 2] = bv; acc[j * 4 + 3] = bv;
            }
            for (int ic = 0; ic < NROT; ic++) {
#pragma unroll
                for (int ky = 0; ky < 3; ky++) {
                    const float* base = s_img + (ic << 12) + ((2 * row + ky) << 6);
                    float4 ef = *(const float4*)(base + 4 * q);
                    float4 of = *(const float4*)(base + 32 + 4 * q);
                    float  e4 = base[4 * q + 4];
                    int r0 = (ic * 9 + ky * 3) << 5;
                    const float4* wp0 = (const float4*)(s_w + r0 + oc0);
                    const float4* wp1 = (const float4*)(s_w + r0 + 32 + oc0);
                    const float4* wp2 = (const float4*)(s_w + r0 + 64 + oc0);
                    fma8x4(acc, ef.x, ef.y, ef.z, ef.w, wp0[0], wp0[1]);
                    fma8x4(acc, of.x, of.y, of.z, of.w, wp1[0], wp1[1]);
                    fma8x4(acc, ef.y, ef.z, ef.w, e4,   wp2[0], wp2[1]);
                }
            }
#pragma unroll
            for (int j = 0; j < 8; j++) {
                float* o = g_c1 + (((size_t)b * 32 + oc0 + j) * 31 + row) * 32;
#pragma unroll
                for (int l = 0; l < 4; l++) {
                    int px = 4 * q + l;
                    if (px < 31)
                        o[((px & 1) << 4) + (px >> 1)] = leaky(acc[j * 4 + l]);
                }
            }
        }
    }
}

// ---------------- conv2: 32ch 31x31 -> 64ch 15x15 (per-batch block) ---------
__global__ void __launch_bounds__(512, 1) k_conv2(const float* __restrict__ bias) {
    extern __shared__ float sm[];
    float* s_in = sm;                     // 32*31*32 = 31744
    float* s_w  = sm + 31744;             // 288*64 = 18432
    int b = blockIdx.x, t = threadIdx.x;
    const float4* in4 = (const float4*)(g_c1 + (size_t)b * 31744);
    for (int i = t; i < 31744 / 4; i += 512) ((float4*)s_in)[i] = in4[i];
    for (int i = t; i < 18432 / 4; i += 512)
        ((float4*)s_w)[i] = ((const float4*)g_wt2)[i];
    __syncthreads();

    int ocg = t >> 6;                     // 8 groups of 8 oc
    int oc0 = ocg << 3;
    int pxg = t & 63;                     // 15 rows x 4 quads = 60 active
    int row = pxg >> 2, q = pxg & 3;
    if (pxg >= 60) return;
    float acc[32];
#pragma unroll
    for (int j = 0; j < 8; j++) {
        float bv = __ldg(&bias[oc0 + j]);
        acc[j * 4] = bv; acc[j * 4 + 1] = bv;
        acc[j * 4 + 2] = bv; acc[j * 4 + 3] = bv;
    }
    for (int ic = 0; ic < 32; ic++) {
#pragma unroll
        for (int ky = 0; ky < 3; ky++) {
            const float* base = s_in + ic * 992 + (2 * row + ky) * 32;
            float4 ef = *(const float4*)(base + 4 * q);
            float4 of = *(const float4*)(base + 16 + 4 * q);
            float  e4 = base[4 * q + 4];
            int r0 = (ic * 9 + ky * 3) << 6;
            const float4* wp0 = (const float4*)(s_w + r0 + oc0);
            const float4* wp1 = (const float4*)(s_w + r0 + 64 + oc0);
            const float4* wp2 = (const float4*)(s_w + r0 + 128 + oc0);
            fma8x4(acc, ef.x, ef.y, ef.z, ef.w, wp0[0], wp0[1]);
            fma8x4(acc, of.x, of.y, of.z, of.w, wp1[0], wp1[1]);
            fma8x4(acc, ef.y, ef.z, ef.w, e4,   wp2[0], wp2[1]);
        }
    }
#pragma unroll
    for (int j = 0; j < 8; j++) {
        float* o = g_c2 + (((size_t)b * 64 + oc0 + j) * 15 + row) * 16;
#pragma unroll
        for (int l = 0; l < 4; l++) {
            int px = 4 * q + l;
            if (px < 15)
                o[((px & 1) << 3) + (px >> 1)] = leaky(acc[j * 4 + l]);
        }
    }
}

// ---------------- conv3: 64ch 15x15 -> 128ch 7x7 -> feat --------------------
// One block per b, all 128 oc; weights streamed in two 32-ic chunks.
__global__ void __launch_bounds__(256, 1) k_conv3(const float* __restrict__ bias) {
    extern __shared__ float sm[];
    float* s_in = sm;                     // 64*15*16 = 15360
    float* s_w  = sm + 15360;             // 288*128 = 36864 (one ic-chunk)
    int b = blockIdx.x, t = threadIdx.x;
    const float4* in4 = (const float4*)(g_c2 + (size_t)b * 15360);
    for (int i = t; i < 15360 / 4; i += 256) ((float4*)s_in)[i] = in4[i];

    int ocg = t >> 4;                     // 16 groups of 8 oc
    int oc0 = ocg << 3;
    int pxg = t & 15;                     // 7 rows x 2 quads = 14 active
    int row = pxg >> 1, q = pxg & 1;
    bool active = pxg < 14;

    float acc[32];
#pragma unroll
    for (int j = 0; j < 8; j++) {
        float bv = __ldg(&bias[oc0 + j]);
        acc[j * 4] = bv; acc[j * 4 + 1] = bv;
        acc[j * 4 + 2] = bv; acc[j * 4 + 3] = bv;
    }

    for (int chunk = 0; chunk < 2; chunk++) {
        __syncthreads();
        const float4* wsrc = (const float4*)g_wt3 + chunk * 9216;
        for (int i = t; i < 9216; i += 256) ((float4*)s_w)[i] = wsrc[i];
        __syncthreads();
        if (active) {
            for (int icl = 0; icl < 32; icl++) {
                int ic = chunk * 32 + icl;
#pragma unroll
                for (int ky = 0; ky < 3; ky++) {
                    const float* base = s_in + ic * 240 + (2 * row + ky) * 16;
                    float4 ef = *(const float4*)(base + 4 * q);
                    float4 of = *(const float4*)(base + 8 + 4 * q);
                    float  e4 = base[4 * q + 4];
                    int r0 = (icl * 9 + ky * 3) << 7;
                    const float4* wp0 = (const float4*)(s_w + r0 + oc0);
                    const float4* wp1 = (const float4*)(s_w + r0 + 128 + oc0);
                    const float4* wp2 = (const float4*)(s_w + r0 + 256 + oc0);
                    fma8x4(acc, ef.x, ef.y, ef.z, ef.w, wp0[0], wp0[1]);
                    fma8x4(acc, of.x, of.y, of.z, of.w, wp1[0], wp1[1]);
                    fma8x4(acc, ef.y, ef.z, ef.w, e4,   wp2[0], wp2[1]);
                }
            }
        }
    }
    if (active) {
#pragma unroll
        for (int j = 0; j < 8; j++) {
            float* o = g_feat + (size_t)b * 6272 + (oc0 + j) * 49 + row * 7;
#pragma unroll
            for (int l = 0; l < 4; l++) {
                int px = 4 * q + l;
                if (px < 7) o[px] = leaky(acc[j * 4 + l]);
            }
        }
    }
}

// ---------------- fused dual-head GEMM (split-K, 8x4 reg tiles) -------------
// C[head][512,256] = A[head] * W[head]^T
// grid: x = m-tile (128), y = [0..3]=cls n-tile | [4..7]=reg, z = splitK
__global__ void __launch_bounds__(256) k_gemm(
    const float* __restrict__ Ac, const float* __restrict__ Ar,
    const float* __restrict__ Bc, const float* __restrict__ Br,
    float* __restrict__ part, int K, int Ksplit) {
    __shared__ float sA[16 * 128];        // [k][m]
    __shared__ float sB[16 * 64];         // [k][n]
    int head = blockIdx.y >> 2;
    int m0 = blockIdx.x * 128, n0 = (blockIdx.y & 3) * 64;
    int k0 = blockIdx.z * Ksplit;
    const float* A  = head ? Ar : Ac;
    const float* Bw = head ? Br : Bc;
    int t = threadIdx.x;                  // 256
    // loader mapping
    int a_m = t >> 1, a_f = (t & 1) * 2;            // 2 float4 per thread (A)
    int b_n = t >> 2, b_f = t & 3;                  // 1 float4 per thread (B)
    const float* Ap = A + (size_t)(m0 + a_m) * K + k0;
    const float* Bp = Bw + (size_t)(n0 + b_n) * K + k0;
    int tm = t >> 4, tn = t & 15;
    float acc[32];
#pragma unroll
    for (int i = 0; i < 32; i++) acc[i] = 0.f;
    for (int kk = 0; kk < Ksplit; kk += 16) {
        float4 av0 = *(const float4*)(Ap + kk + a_f * 4);
        float4 av1 = *(const float4*)(Ap + kk + a_f * 4 + 4);
        float4 bv  = *(const float4*)(Bp + kk + b_f * 4);
        __syncthreads();
        sA[(a_f * 4 + 0) * 128 + a_m] = av0.x;
        sA[(a_f * 4 + 1) * 128 + a_m] = av0.y;
        sA[(a_f * 4 + 2) * 128 + a_m] = av0.z;
        sA[(a_f * 4 + 3) * 128 + a_m] = av0.w;
        sA[(a_f * 4 + 4) * 128 + a_m] = av1.x;
        sA[(a_f * 4 + 5) * 128 + a_m] = av1.y;
        sA[(a_f * 4 + 6) * 128 + a_m] = av1.z;
        sA[(a_f * 4 + 7) * 128 + a_m] = av1.w;
        sB[(b_f * 4 + 0) * 64 + b_n] = bv.x;
        sB[(b_f * 4 + 1) * 64 + b_n] = bv.y;
        sB[(b_f * 4 + 2) * 64 + b_n] = bv.z;
        sB[(b_f * 4 + 3) * 64 + b_n] = bv.w;
        __syncthreads();
#pragma unroll
        for (int k = 0; k < 16; k++) {
            float4 a0 = *(const float4*)&sA[k * 128 + tm * 8];
            float4 a1 = *(const float4*)&sA[k * 128 + tm * 8 + 4];
            float4 bq = *(const float4*)&sB[k * 64 + tn * 4];
            float a_[8] = {a0.x, a0.y, a0.z, a0.w, a1.x, a1.y, a1.z, a1.w};
#pragma unroll
            for (int i = 0; i < 8; i++) {
                acc[i * 4 + 0] = fmaf(a_[i], bq.x, acc[i * 4 + 0]);
                acc[i * 4 + 1] = fmaf(a_[i], bq.y, acc[i * 4 + 1]);
                acc[i * 4 + 2] = fmaf(a_[i], bq.z, acc[i * 4 + 2]);
                acc[i * 4 + 3] = fmaf(a_[i], bq.w, acc[i * 4 + 3]);
            }
        }
    }
    float* p = part + (size_t)(blockIdx.z * 2 + head) * (512 * 256);
#pragma unroll
    for (int i = 0; i < 8; i++) {
        float4* rowp = (float4*)(p + (size_t)(m0 + tm * 8 + i) * 256 + n0 + tn * 4);
        *rowp = make_float4(acc[i * 4], acc[i * 4 + 1], acc[i * 4 + 2], acc[i * 4 + 3]);
    }
}

// ---------------- split-K reduce + bias + relu (both heads) -----------------
__global__ void k_reduce(const float* __restrict__ part,
                         const float* __restrict__ cb, const float* __restrict__ rb,
                         float* __restrict__ out, int S) {
    int i = blockIdx.x * 256 + threadIdx.x;        // over 2*512*256
    int head = i >> 17;
    int j = i & 131071;
    float v = 0.f;
    for (int s = 0; s < S; s++) v += part[(size_t)(s * 2 + head) * 131072 + j];
    v += (head ? rb : cb)[j & 255];
    out[i] = fmaxf(v, 0.f);
}

// ---------------- final heads ----------------------------------------------
__global__ void k_fc3(const float* __restrict__ cw, const float* __restrict__ cb,
                      const float* __restrict__ rw, const float* __restrict__ rb,
                      float* __restrict__ out) {
    __shared__ float hc[256], hr[256];
    int b = blockIdx.x, t = threadIdx.x;           // 64 threads
    for (int i = t; i < 256; i += 64) {
        hc[i] = g_h2[b * 256 + i];
        hr[i] = g_h2[131072 + b * 256 + i];
    }
    __syncthreads();
    if (t >= 47) return;
    const float* w = (t == 0) ? cw : rw + (t - 1) * 256;
    const float* h = (t == 0) ? hc : hr;
    float acc = (t == 0) ? cb[0] : rb[t - 1];
    for (int k = 0; k < 256; k++) acc = fmaf(h[k], w[k], acc);
    if (t == 0) out[b] = acc;
    else        out[512 + b * 46 + (t - 1)] = acc;
}

// ---------------- launch ----------------------------------------------------
extern "C" void kernel_launch(void* const* d_in, const int* in_sizes, int n_in,
                              void* d_out, int out_size) {
    const float* pts = (const float*)d_in[0];
    const float* rot = (const float*)d_in[1];
    const float* w1  = (const float*)d_in[2];  const float* b1  = (const float*)d_in[3];
    const float* w2  = (const float*)d_in[4];  const float* b2  = (const float*)d_in[5];
    const float* w3  = (const float*)d_in[6];  const float* b3  = (const float*)d_in[7];
    const float* cw1 = (const float*)d_in[8];  const float* cb1 = (const float*)d_in[9];
    const float* cw2 = (const float*)d_in[10]; const float* cb2 = (const float*)d_in[11];
    const float* cw3 = (const float*)d_in[12]; const float* cb3 = (const float*)d_in[13];
    const float* rw1 = (const float*)d_in[14]; const float* rb1 = (const float*)d_in[15];
    const float* rw2 = (const float*)d_in[16]; const float* rb2 = (const float*)d_in[17];
    const float* rw3 = (const float*)d_in[18]; const float* rb3 = (const float*)d_in[19];
    float* out = (float*)d_out;

    float *featp, *h1p, *h2p, *partp;
    cudaGetSymbolAddress((void**)&featp, g_feat);
    cudaGetSymbolAddress((void**)&h1p, g_h1);
    cudaGetSymbolAddress((void**)&h2p, g_h2);
    cudaGetSymbolAddress((void**)&partp, g_part);

    const int SM1 = (49152 + 3456 + 1536 + 128) * 4;   // 217,088 B
    const int SM2 = (31744 + 18432) * 4;               // 200,704 B
    const int SM3 = (15360 + 36864) * 4;               // 208,896 B
    cudaFuncSetAttribute(k_fuse1, cudaFuncAttributeMaxDynamicSharedMemorySize, SM1);
    cudaFuncSetAttribute(k_conv2, cudaFuncAttributeMaxDynamicSharedMemorySize, SM2);
    cudaFuncSetAttribute(k_conv3, cudaFuncAttributeMaxDynamicSharedMemorySize, SM3);

    k_prep<<<(3456 + 18432 + 73728 + 255) / 256, 256>>>(w1, w2, w3);
    k_fuse1<<<BATCH, 512, SM1>>>(pts, rot, b1);
    k_conv2<<<BATCH, 512, SM2>>>(b2);
    k_conv3<<<BATCH, 256, SM3>>>(b3);
    k_gemm<<<dim3(4, 8, 4), 256>>>(featp, featp, cw1, rw1, partp, 6272, 1568);
    k_reduce<<<1024, 256>>>(partp, cb1, rb1, h1p, 4);
    k_gemm<<<dim3(4, 8, 2), 256>>>(h1p, h1p + 131072, cw2, rw2, partp, 256, 128);
    k_reduce<<<1024, 256>>>(partp, cb2, rb2, h2p, 2);
    k_fc3<<<BATCH, 64>>>(cw3, cb3, rw3, rb3, out);
    (void)in_sizes; (void)n_in; (void)out_size;
}

// round 8
// speedup vs baseline: 1.9289x; 1.0433x over previous
#include <cuda_runtime.h>

#define BATCH 512
#define NPTS  512
#define NROT  12
#define IMG   64

// padded strides (bank-conflict-free for stride-2 quad reads)
#define C1_ROW 40
#define C1_IC  1240               // 31 * 40
#define C2_ROW 20
#define C2_IC  304                // 15*20=300, padded to 16B multiple

// ---------------- scratch (device globals; no allocations allowed) ----------
__device__ float g_c1[BATCH * 32 * C1_IC];            // 81 MB
__device__ float g_c2[BATCH * 64 * C2_IC];            // 40 MB
__device__ float g_feat[BATCH * 6272];                // 12.8 MB
__device__ float g_h1[2 * BATCH * 256];
__device__ float g_h2[2 * BATCH * 256];
__device__ float g_part[28 * BATCH * 256];            // [split*2+head][b][n]
__device__ float g_wt1[108 * 32];                     // [r][oc]
__device__ float g_wt2[288 * 64];                     // [r][oc]
__device__ float g_wt3[576 * 128];                    // [r][oc] (merged halves)

__device__ __forceinline__ float leaky(float v) {
    return v >= 0.f ? v : 0.2f * v;
}

// 8 oc x 4 px outer-product FMA block
__device__ __forceinline__ void fma8x4(float* acc, float v0, float v1,
                                       float v2, float v3,
                                       float4 w0, float4 w1) {
    float w[8] = {w0.x, w0.y, w0.z, w0.w, w1.x, w1.y, w1.z, w1.w};
#pragma unroll
    for (int j = 0; j < 8; j++) {
        acc[j * 4 + 0] = fmaf(v0, w[j], acc[j * 4 + 0]);
        acc[j * 4 + 1] = fmaf(v1, w[j], acc[j * 4 + 1]);
        acc[j * 4 + 2] = fmaf(v2, w[j], acc[j * 4 + 2]);
        acc[j * 4 + 3] = fmaf(v3, w[j], acc[j * 4 + 3]);
    }
}

// ---------------- weight prep: transpose (OC,R) -> (R,OC) -------------------
__global__ void k_prep(const float* __restrict__ w1, const float* __restrict__ w2,
                       const float* __restrict__ w3) {
    int i = blockIdx.x * 256 + threadIdx.x;
    if (i < 3456) {
        int r = i >> 5, oc = i & 31;
        g_wt1[i] = w1[oc * 108 + r];
        return;
    }
    i -= 3456;
    if (i < 18432) {
        int r = i >> 6, oc = i & 63;
        g_wt2[i] = w2[oc * 288 + r];
        return;
    }
    i -= 18432;
    if (i < 73728) {
        int r = i >> 7, oc = i & 127;
        g_wt3[i] = w3[oc * 576 + r];
    }
}

// ---------------- fused scatter + conv1 (per-batch block) -------------------
__global__ void __launch_bounds__(512, 1) k_fuse1(
    const float* __restrict__ pts, const float* __restrict__ rot,
    const float* __restrict__ bias) {
    extern __shared__ float sm[];
    float* s_img = sm;                    // 49152 floats (12 x 64 x 64 deint-x)
    float* s_w   = sm + 49152;            // 3456
    float* s_pts = s_w + 3456;            // 1536
    float* s_rot = s_pts + 1536;          // 108
    unsigned int* u_img = (unsigned int*)s_img;
    int b = blockIdx.x, t = threadIdx.x;

    for (int i = t; i < 49152 / 4; i += 512)
        ((uint4*)u_img)[i] = make_uint4(0u, 0u, 0u, 0u);
    for (int i = t; i < 1536; i += 512) s_pts[i] = pts[b * 1536 + i];
    if (t < 108) s_rot[t] = rot[t];
    for (int i = t; i < 3456 / 4; i += 512)
        ((float4*)s_w)[i] = ((const float4*)g_wt1)[i];
    __syncthreads();

    // scatter: key = (n<<23) | (valbits>>9); atomicMax => last point index wins
    for (int task = t; task < NROT * NPTS; task += 512) {
        int m = task >> 9, n = task & 511;
        float x = s_pts[n * 3], y = s_pts[n * 3 + 1], z = s_pts[n * 3 + 2];
        const float* r = s_rot + m * 9;
        float xr = r[0] * x + r[1] * y + r[2] * z;
        float zr = r[6] * x + r[7] * y + r[8] * z;
        float fx = rintf((xr + 2.0f) / 0.0625f);   // round-half-even == jnp.round
        float fy = rintf((y + 2.0f) / 0.0625f);
        int px = (int)fx, py = (int)fy;
        bool ok = (px >= 0) && (px < IMG) && (py >= 0) && (py < IMG);
        if (!ok) { px = 0; py = 0; }               // proj*ok -> OOB hits (0,0)
        float val = zr / 10.0f;
        unsigned int key = ((unsigned int)n << 23) | (__float_as_uint(val) >> 9);
        int didx = ((px & 1) << 5) + (px >> 1);    // deinterleave x
        atomicMax(&u_img[(m << 12) + (py << 6) + didx], key);
    }
    __syncthreads();
    for (int i = t; i < 49152 / 4; i += 512) {
        uint4 v = ((uint4*)u_img)[i];
        v.x = (v.x & 0x7fffffu) << 9; v.y = (v.y & 0x7fffffu) << 9;
        v.z = (v.z & 0x7fffffu) << 9; v.w = (v.w & 0x7fffffu) << 9;
        ((uint4*)u_img)[i] = v;                    // decode to float bits
    }
    __syncthreads();

    // conv1: 12ch 64x64 -> 32ch 31x31 stride-2 leaky.
    int pxg = t & 255;
    int row = pxg >> 3, q = pxg & 7;
    bool active = pxg < 248;                        // 31 rows x 8 quads
#pragma unroll
    for (int uu = 0; uu < 2; uu++) {
        int ocg = (t >> 8) + 2 * uu;                // 0..3
        int oc0 = ocg << 3;
        if (active) {
            float acc[32];
#pragma unroll
            for (int j = 0; j < 8; j++) {
                float bv = __ldg(&bias[oc0 + j]);
                acc[j * 4] = bv; acc[j * 4 + 1] = bv;
                acc[j * 4 + 2] = bv; acc[j * 4 + 3] = bv;
            }
            for (int ic = 0; ic < NROT; ic++) {
#pragma unroll
                for (int ky = 0; ky < 3; ky++) {
                    const float* base = s_img + (ic << 12) + ((2 * row + ky) << 6);
                    float4 ef = *(const float4*)(base + 4 * q);
                    float4 of = *(const float4*)(base + 32 + 4 * q);
                    float  e4 = base[4 * q + 4];
                    int r0 = (ic * 9 + ky * 3) << 5;
                    const float4* wp0 = (const float4*)(s_w + r0 + oc0);
                    const float4* wp1 = (const float4*)(s_w + r0 + 32 + oc0);
                    const float4* wp2 = (const float4*)(s_w + r0 + 64 + oc0);
                    fma8x4(acc, ef.x, ef.y, ef.z, ef.w, wp0[0], wp0[1]);
                    fma8x4(acc, of.x, of.y, of.z, of.w, wp1[0], wp1[1]);
                    fma8x4(acc, ef.y, ef.z, ef.w, e4,   wp2[0], wp2[1]);
                }
            }
#pragma unroll
            for (int j = 0; j < 8; j++) {
                float* o = g_c1 + ((size_t)b * 32 + oc0 + j) * C1_IC + row * C1_ROW;
#pragma unroll
                for (int l = 0; l < 4; l++) {
                    int px = 4 * q + l;
                    if (px < 31)
                        o[((px & 1) << 4) + (px >> 1)] = leaky(acc[j * 4 + l]);
                }
            }
        }
    }
}

// ---------------- conv2: 32ch 31x31 -> 64ch 15x15 (per-batch block) ---------
// weights streamed in two 16-ic chunks; input padded stride (conflict-free)
__global__ void __launch_bounds__(512, 1) k_conv2(const float* __restrict__ bias) {
    extern __shared__ float sm[];
    float* s_in = sm;                     // 32*1240 = 39680
    float* s_w  = sm + 39680;             // 16*9*64 = 9216 (one ic-chunk)
    int b = blockIdx.x, t = threadIdx.x;
    const float4* in4 = (const float4*)(g_c1 + (size_t)b * (32 * C1_IC));
    for (int i = t; i < 39680 / 4; i += 512) ((float4*)s_in)[i] = in4[i];

    int ocg = t >> 6;                     // 8 groups of 8 oc
    int oc0 = ocg << 3;
    int pxg = t & 63;                     // 15 rows x 4 quads = 60 active
    int row = pxg >> 2, q = pxg & 3;
    bool active = pxg < 60;
    float acc[32];
#pragma unroll
    for (int j = 0; j < 8; j++) {
        float bv = __ldg(&bias[oc0 + j]);
        acc[j * 4] = bv; acc[j * 4 + 1] = bv;
        acc[j * 4 + 2] = bv; acc[j * 4 + 3] = bv;
    }
    for (int chunk = 0; chunk < 2; chunk++) {
        __syncthreads();
        const float4* wsrc = (const float4*)g_wt2 + chunk * 2304;
        for (int i = t; i < 2304; i += 512) ((float4*)s_w)[i] = wsrc[i];
        __syncthreads();
        if (active) {
            for (int icl = 0; icl < 16; icl++) {
                int ic = chunk * 16 + icl;
#pragma unroll
                for (int ky = 0; ky < 3; ky++) {
                    const float* base = s_in + ic * C1_IC + (2 * row + ky) * C1_ROW;
                    float4 ef = *(const float4*)(base + 4 * q);
                    float4 of = *(const float4*)(base + 16 + 4 * q);
                    float  e4 = base[4 * q + 4];
                    int r0 = (icl * 9 + ky * 3) << 6;
                    const float4* wp0 = (const float4*)(s_w + r0 + oc0);
                    const float4* wp1 = (const float4*)(s_w + r0 + 64 + oc0);
                    const float4* wp2 = (const float4*)(s_w + r0 + 128 + oc0);
                    fma8x4(acc, ef.x, ef.y, ef.z, ef.w, wp0[0], wp0[1]);
                    fma8x4(acc, of.x, of.y, of.z, of.w, wp1[0], wp1[1]);
                    fma8x4(acc, ef.y, ef.z, ef.w, e4,   wp2[0], wp2[1]);
                }
            }
        }
    }
    if (active) {
#pragma unroll
        for (int j = 0; j < 8; j++) {
            float* o = g_c2 + ((size_t)b * 64 + oc0 + j) * C2_IC + row * C2_ROW;
#pragma unroll
            for (int l = 0; l < 4; l++) {
                int px = 4 * q + l;
                if (px < 15)
                    o[((px & 1) << 3) + (px >> 1)] = leaky(acc[j * 4 + l]);
            }
        }
    }
}

// ---------------- conv3: 64ch 15x15 -> 128ch 7x7 -> feat --------------------
// One block per b, all 128 oc; weights streamed in two 32-ic chunks.
__global__ void __launch_bounds__(256, 1) k_conv3(const float* __restrict__ bias) {
    extern __shared__ float sm[];
    float* s_in = sm;                     // 64*304 = 19456
    float* s_w  = sm + 19456;             // 32*9*128 = 36864 (one ic-chunk)
    int b = blockIdx.x, t = threadIdx.x;
    const float4* in4 = (const float4*)(g_c2 + (size_t)b * (64 * C2_IC));
    for (int i = t; i < 19456 / 4; i += 256) ((float4*)s_in)[i] = in4[i];

    int ocg = t >> 4;                     // 16 groups of 8 oc
    int oc0 = ocg << 3;
    int pxg = t & 15;                     // 7 rows x 2 quads = 14 active
    int row = pxg >> 1, q = pxg & 1;
    bool active = pxg < 14;

    float acc[32];
#pragma unroll
    for (int j = 0; j < 8; j++) {
        float bv = __ldg(&bias[oc0 + j]);
        acc[j * 4] = bv; acc[j * 4 + 1] = bv;
        acc[j * 4 + 2] = bv; acc[j * 4 + 3] = bv;
    }

    for (int chunk = 0; chunk < 2; chunk++) {
        __syncthreads();
        const float4* wsrc = (const float4*)g_wt3 + chunk * 9216;
        for (int i = t; i < 9216; i += 256) ((float4*)s_w)[i] = wsrc[i];
        __syncthreads();
        if (active) {
            for (int icl = 0; icl < 32; icl++) {
                int ic = chunk * 32 + icl;
#pragma unroll
                for (int ky = 0; ky < 3; ky++) {
                    const float* base = s_in + ic * C2_IC + (2 * row + ky) * C2_ROW;
                    float4 ef = *(const float4*)(base + 4 * q);
                    float4 of = *(const float4*)(base + 8 + 4 * q);
                    float  e4 = base[4 * q + 4];
                    int r0 = (icl * 9 + ky * 3) << 7;
                    const float4* wp0 = (const float4*)(s_w + r0 + oc0);
                    const float4* wp1 = (const float4*)(s_w + r0 + 128 + oc0);
                    const float4* wp2 = (const float4*)(s_w + r0 + 256 + oc0);
                    fma8x4(acc, ef.x, ef.y, ef.z, ef.w, wp0[0], wp0[1]);
                    fma8x4(acc, of.x, of.y, of.z, of.w, wp1[0], wp1[1]);
                    fma8x4(acc, ef.y, ef.z, ef.w, e4,   wp2[0], wp2[1]);
                }
            }
        }
    }
    if (active) {
#pragma unroll
        for (int j = 0; j < 8; j++) {
            float* o = g_feat + (size_t)b * 6272 + (oc0 + j) * 49 + row * 7;
#pragma unroll
            for (int l = 0; l < 4; l++) {
                int px = 4 * q + l;
                if (px < 7) o[px] = leaky(acc[j * 4 + l]);
            }
        }
    }
}

// ---------------- fused dual-head GEMM (split-K, 8x4 reg tiles) -------------
__global__ void __launch_bounds__(256) k_gemm(
    const float* __restrict__ Ac, const float* __restrict__ Ar,
    const float* __restrict__ Bc, const float* __restrict__ Br,
    float* __restrict__ part, int K, int Ksplit) {
    __shared__ float sA[16 * 128];        // [k][m]
    __shared__ float sB[16 * 64];         // [k][n]
    int head = blockIdx.y >> 2;
    int m0 = blockIdx.x * 128, n0 = (blockIdx.y & 3) * 64;
    int k0 = blockIdx.z * Ksplit;
    const float* A  = head ? Ar : Ac;
    const float* Bw = head ? Br : Bc;
    int t = threadIdx.x;                  // 256
    int a_m = t >> 1, a_f = (t & 1) * 2;            // 2 float4 per thread (A)
    int b_n = t >> 2, b_f = t & 3;                  // 1 float4 per thread (B)
    const float* Ap = A + (size_t)(m0 + a_m) * K + k0;
    const float* Bp = Bw + (size_t)(n0 + b_n) * K + k0;
    int tm = t >> 4, tn = t & 15;
    float acc[32];
#pragma unroll
    for (int i = 0; i < 32; i++) acc[i] = 0.f;
    for (int kk = 0; kk < Ksplit; kk += 16) {
        float4 av0 = *(const float4*)(Ap + kk + a_f * 4);
        float4 av1 = *(const float4*)(Ap + kk + a_f * 4 + 4);
        float4 bv  = *(const float4*)(Bp + kk + b_f * 4);
        __syncthreads();
        sA[(a_f * 4 + 0) * 128 + a_m] = av0.x;
        sA[(a_f * 4 + 1) * 128 + a_m] = av0.y;
        sA[(a_f * 4 + 2) * 128 + a_m] = av0.z;
        sA[(a_f * 4 + 3) * 128 + a_m] = av0.w;
        sA[(a_f * 4 + 4) * 128 + a_m] = av1.x;
        sA[(a_f * 4 + 5) * 128 + a_m] = av1.y;
        sA[(a_f * 4 + 6) * 128 + a_m] = av1.z;
        sA[(a_f * 4 + 7) * 128 + a_m] = av1.w;
        sB[(b_f * 4 + 0) * 64 + b_n] = bv.x;
        sB[(b_f * 4 + 1) * 64 + b_n] = bv.y;
        sB[(b_f * 4 + 2) * 64 + b_n] = bv.z;
        sB[(b_f * 4 + 3) * 64 + b_n] = bv.w;
        __syncthreads();
#pragma unroll
        for (int k = 0; k < 16; k++) {
            float4 a0 = *(const float4*)&sA[k * 128 + tm * 8];
            float4 a1 = *(const float4*)&sA[k * 128 + tm * 8 + 4];
            float4 bq = *(const float4*)&sB[k * 64 + tn * 4];
            float a_[8] = {a0.x, a0.y, a0.z, a0.w, a1.x, a1.y, a1.z, a1.w};
#pragma unroll
            for (int i = 0; i < 8; i++) {
                acc[i * 4 + 0] = fmaf(a_[i], bq.x, acc[i * 4 + 0]);
                acc[i * 4 + 1] = fmaf(a_[i], bq.y, acc[i * 4 + 1]);
                acc[i * 4 + 2] = fmaf(a_[i], bq.z, acc[i * 4 + 2]);
                acc[i * 4 + 3] = fmaf(a_[i], bq.w, acc[i * 4 + 3]);
            }
        }
    }
    float* p = part + (size_t)(blockIdx.z * 2 + head) * (512 * 256);
#pragma unroll
    for (int i = 0; i < 8; i++) {
        float4* rowp = (float4*)(p + (size_t)(m0 + tm * 8 + i) * 256 + n0 + tn * 4);
        *rowp = make_float4(acc[i * 4], acc[i * 4 + 1], acc[i * 4 + 2], acc[i * 4 + 3]);
    }
}

// ---------------- split-K reduce + bias + relu (both heads) -----------------
__global__ void k_reduce(const float* __restrict__ part,
                         const float* __restrict__ cb, const float* __restrict__ rb,
                         float* __restrict__ out, int S) {
    int i = blockIdx.x * 256 + threadIdx.x;        // over 2*512*256
    int head = i >> 17;
    int j = i & 131071;
    float v = 0.f;
    for (int s = 0; s < S; s++) v += part[(size_t)(s * 2 + head) * 131072 + j];
    v += (head ? rb : cb)[j & 255];
    out[i] = fmaxf(v, 0.f);
}

// ---------------- final heads ----------------------------------------------
__global__ void k_fc3(const float* __restrict__ cw, const float* __restrict__ cb,
                      const float* __restrict__ rw, const float* __restrict__ rb,
                      float* __restrict__ out) {
    __shared__ float hc[256], hr[256];
    int b = blockIdx.x, t = threadIdx.x;           // 64 threads
    for (int i = t; i < 256; i += 64) {
        hc[i] = g_h2[b * 256 + i];
        hr[i] = g_h2[131072 + b * 256 + i];
    }
    __syncthreads();
    if (t >= 47) return;
    const float* w = (t == 0) ? cw : rw + (t - 1) * 256;
    const float* h = (t == 0) ? hc : hr;
    float acc = (t == 0) ? cb[0] : rb[t - 1];
    for (int k = 0; k < 256; k++) acc = fmaf(h[k], w[k], acc);
    if (t == 0) out[b] = acc;
    else        out[512 + b * 46 + (t - 1)] = acc;
}

// ---------------- launch ----------------------------------------------------
extern "C" void kernel_launch(void* const* d_in, const int* in_sizes, int n_in,
                              void* d_out, int out_size) {
    const float* pts = (const float*)d_in[0];
    const float* rot = (const float*)d_in[1];
    const float* w1  = (const float*)d_in[2];  const float* b1  = (const float*)d_in[3];
    const float* w2  = (const float*)d_in[4];  const float* b2  = (const float*)d_in[5];
    const float* w3  = (const float*)d_in[6];  const float* b3  = (const float*)d_in[7];
    const float* cw1 = (const float*)d_in[8];  const float* cb1 = (const float*)d_in[9];
    const float* cw2 = (const float*)d_in[10]; const float* cb2 = (const float*)d_in[11];
    const float* cw3 = (const float*)d_in[12]; const float* cb3 = (const float*)d_in[13];
    const float* rw1 = (const float*)d_in[14]; const float* rb1 = (const float*)d_in[15];
    const float* rw2 = (const float*)d_in[16]; const float* rb2 = (const float*)d_in[17];
    const float* rw3 = (const float*)d_in[18]; const float* rb3 = (const float*)d_in[19];
    float* out = (float*)d_out;

    float *featp, *h1p, *h2p, *partp;
    cudaGetSymbolAddress((void**)&featp, g_feat);
    cudaGetSymbolAddress((void**)&h1p, g_h1);
    cudaGetSymbolAddress((void**)&h2p, g_h2);
    cudaGetSymbolAddress((void**)&partp, g_part);

    const int SM1 = (49152 + 3456 + 1536 + 128) * 4;   // 217,088 B
    const int SM2 = (39680 + 9216) * 4;                // 195,584 B
    const int SM3 = (19456 + 36864) * 4;               // 225,280 B
    cudaFuncSetAttribute(k_fuse1, cudaFuncAttributeMaxDynamicSharedMemorySize, SM1);
    cudaFuncSetAttribute(k_conv2, cudaFuncAttributeMaxDynamicSharedMemorySize, SM2);
    cudaFuncSetAttribute(k_conv3, cudaFuncAttributeMaxDynamicSharedMemorySize, SM3);

    k_prep<<<(3456 + 18432 + 73728 + 255) / 256, 256>>>(w1, w2, w3);
    k_fuse1<<<BATCH, 512, SM1>>>(pts, rot, b1);
    k_conv2<<<BATCH, 512, SM2>>>(b2);
    k_conv3<<<BATCH, 256, SM3>>>(b3);
    k_gemm<<<dim3(4, 8, 14), 256>>>(featp, featp, cw1, rw1, partp, 6272, 448);
    k_reduce<<<1024, 256>>>(partp, cb1, rb1, h1p, 14);
    k_gemm<<<dim3(4, 8, 2), 256>>>(h1p, h1p + 131072, cw2, rw2, partp, 256, 128);
    k_reduce<<<1024, 256>>>(partp, cb2, rb2, h2p, 2);
    k_fc3<<<BATCH, 64>>>(cw3, cb3, rw3, rb3, out);
    (void)in_sizes; (void)n_in; (void)out_size;
}

// round 9
// speedup vs baseline: 2.2486x; 1.1657x over previous
#include <cuda_runtime.h>

#define BATCH 512
#define NPTS  512
#define NROT  12
#define IMG   64

// padded strides (bank-conflict-free for stride-2 quad reads)
#define C1_ROW 40
#define C1_IC  1240               // 31 * 40
#define C2_ROW 20
#define C2_IC  300                // 15 * 20

// ---------------- scratch (device globals; no allocations allowed) ----------
__device__ float g_c1[BATCH * 32 * C1_IC];            // 81 MB
__device__ float g_c2[BATCH * 64 * C2_IC];            // 39.3 MB
__device__ float g_feat[BATCH * 6272];                // 12.8 MB
__device__ float g_h1[2 * BATCH * 256];
__device__ float g_h2[2 * BATCH * 256];
__device__ float g_part[28 * BATCH * 256];            // [split*2+head][b][n]
__device__ float g_wt1[108 * 32];                     // [r][oc]
__device__ float g_wt2[288 * 64];                     // [r][oc]
__device__ float g_wt3[576 * 128];                    // [r][oc] (merged halves)

__device__ __forceinline__ float leaky(float v) {
    return v >= 0.f ? v : 0.2f * v;
}

// 8 oc x 4 px outer-product FMA block
__device__ __forceinline__ void fma8x4(float* acc, float v0, float v1,
                                       float v2, float v3,
                                       float4 w0, float4 w1) {
    float w[8] = {w0.x, w0.y, w0.z, w0.w, w1.x, w1.y, w1.z, w1.w};
#pragma unroll
    for (int j = 0; j < 8; j++) {
        acc[j * 4 + 0] = fmaf(v0, w[j], acc[j * 4 + 0]);
        acc[j * 4 + 1] = fmaf(v1, w[j], acc[j * 4 + 1]);
        acc[j * 4 + 2] = fmaf(v2, w[j], acc[j * 4 + 2]);
        acc[j * 4 + 3] = fmaf(v3, w[j], acc[j * 4 + 3]);
    }
}

// ---------------- weight prep: transpose (OC,R) -> (R,OC) -------------------
__global__ void k_prep(const float* __restrict__ w1, const float* __restrict__ w2,
                       const float* __restrict__ w3) {
    int i = blockIdx.x * 256 + threadIdx.x;
    if (i < 3456) {
        int r = i >> 5, oc = i & 31;
        g_wt1[i] = w1[oc * 108 + r];
        return;
    }
    i -= 3456;
    if (i < 18432) {
        int r = i >> 6, oc = i & 63;
        g_wt2[i] = w2[oc * 288 + r];
        return;
    }
    i -= 18432;
    if (i < 73728) {
        int r = i >> 7, oc = i & 127;
        g_wt3[i] = w3[oc * 576 + r];
    }
}

// ---------------- fused scatter + conv1 (per-batch block) -------------------
__global__ void __launch_bounds__(512, 1) k_fuse1(
    const float* __restrict__ pts, const float* __restrict__ rot,
    const float* __restrict__ bias) {
    extern __shared__ float sm[];
    float* s_img = sm;                    // 49152 floats (12 x 64 x 64 deint-x)
    float* s_w   = sm + 49152;            // 3456
    float* s_pts = s_w + 3456;            // 1536
    float* s_rot = s_pts + 1536;          // 108
    unsigned int* u_img = (unsigned int*)s_img;
    int b = blockIdx.x, t = threadIdx.x;

    for (int i = t; i < 49152 / 4; i += 512)
        ((uint4*)u_img)[i] = make_uint4(0u, 0u, 0u, 0u);
    for (int i = t; i < 1536; i += 512) s_pts[i] = pts[b * 1536 + i];
    if (t < 108) s_rot[t] = rot[t];
    for (int i = t; i < 3456 / 4; i += 512)
        ((float4*)s_w)[i] = ((const float4*)g_wt1)[i];
    __syncthreads();

    // scatter: key = (n<<23) | (valbits>>9); atomicMax => last point index wins
    for (int task = t; task < NROT * NPTS; task += 512) {
        int m = task >> 9, n = task & 511;
        float x = s_pts[n * 3], y = s_pts[n * 3 + 1], z = s_pts[n * 3 + 2];
        const float* r = s_rot + m * 9;
        float xr = r[0] * x + r[1] * y + r[2] * z;
        float zr = r[6] * x + r[7] * y + r[8] * z;
        float fx = rintf((xr + 2.0f) / 0.0625f);   // round-half-even == jnp.round
        float fy = rintf((y + 2.0f) / 0.0625f);
        int px = (int)fx, py = (int)fy;
        bool ok = (px >= 0) && (px < IMG) && (py >= 0) && (py < IMG);
        if (!ok) { px = 0; py = 0; }               // proj*ok -> OOB hits (0,0)
        float val = zr / 10.0f;
        unsigned int key = ((unsigned int)n << 23) | (__float_as_uint(val) >> 9);
        int didx = ((px & 1) << 5) + (px >> 1);    // deinterleave x
        atomicMax(&u_img[(m << 12) + (py << 6) + didx], key);
    }
    __syncthreads();
    for (int i = t; i < 49152 / 4; i += 512) {
        uint4 v = ((uint4*)u_img)[i];
        v.x = (v.x & 0x7fffffu) << 9; v.y = (v.y & 0x7fffffu) << 9;
        v.z = (v.z & 0x7fffffu) << 9; v.w = (v.w & 0x7fffffu) << 9;
        ((uint4*)u_img)[i] = v;                    // decode to float bits
    }
    __syncthreads();

    // conv1: 12ch 64x64 -> 32ch 31x31 stride-2 leaky.
    int pxg = t & 255;
    int row = pxg >> 3, q = pxg & 7;
    bool active = pxg < 248;                        // 31 rows x 8 quads
#pragma unroll
    for (int uu = 0; uu < 2; uu++) {
        int ocg = (t >> 8) + 2 * uu;                // 0..3
        int oc0 = ocg << 3;
        if (active) {
            float acc[32];
#pragma unroll
            for (int j = 0; j < 8; j++) {
                float bv = __ldg(&bias[oc0 + j]);
                acc[j * 4] = bv; acc[j * 4 + 1] = bv;
                acc[j * 4 + 2] = bv; acc[j * 4 + 3] = bv;
            }
            for (int ic = 0; ic < NROT; ic++) {
#pragma unroll
                for (int ky = 0; ky < 3; ky++) {
                    const float* base = s_img + (ic << 12) + ((2 * row + ky) << 6);
                    float4 ef = *(const float4*)(base + 4 * q);
                    float4 of = *(const float4*)(base + 32 + 4 * q);
                    float  e4 = base[4 * q + 4];
                    int r0 = (ic * 9 + ky * 3) << 5;
                    const float4* wp0 = (const float4*)(s_w + r0 + oc0);
                    const float4* wp1 = (const float4*)(s_w + r0 + 32 + oc0);
                    const float4* wp2 = (const float4*)(s_w + r0 + 64 + oc0);
                    fma8x4(acc, ef.x, ef.y, ef.z, ef.w, wp0[0], wp0[1]);
                    fma8x4(acc, of.x, of.y, of.z, of.w, wp1[0], wp1[1]);
                    fma8x4(acc, ef.y, ef.z, ef.w, e4,   wp2[0], wp2[1]);
                }
            }
#pragma unroll
            for (int j = 0; j < 8; j++) {
                float* o = g_c1 + ((size_t)b * 32 + oc0 + j) * C1_IC + row * C1_ROW;
#pragma unroll
                for (int l = 0; l < 4; l++) {
                    int px = 4 * q + l;
                    if (px < 31)
                        o[((px & 1) << 4) + (px >> 1)] = leaky(acc[j * 4 + l]);
                }
            }
        }
    }
}

// ---------------- conv2: 32ch 31x31 -> 64ch 15x15 ---------------------------
// grid (b, oc-half); input AND weights streamed in 4 chunks of 8 ic.
// smem 48.9 KB -> 3 blocks/SM (24 warps).
__global__ void __launch_bounds__(256, 3) k_conv2(const float* __restrict__ bias) {
    extern __shared__ float sm[];
    float* s_in = sm;                     // 8 * 1240 = 9920 fl
    float* s_w  = sm + 9920;              // 8*9*32 = 2304 fl
    int b = blockIdx.x, half = blockIdx.y, t = threadIdx.x;

    int ocg = t >> 6;                     // 4 groups of 8 oc
    int ocl = ocg << 3;                   // local oc in half
    int oc0 = half * 32 + ocl;
    int pxg = t & 63;                     // 15 rows x 4 quads = 60 active
    int row = pxg >> 2, q = pxg & 3;
    bool active = pxg < 60;
    float acc[32];
#pragma unroll
    for (int j = 0; j < 8; j++) {
        float bv = __ldg(&bias[oc0 + j]);
        acc[j * 4] = bv; acc[j * 4 + 1] = bv;
        acc[j * 4 + 2] = bv; acc[j * 4 + 3] = bv;
    }
    for (int chunk = 0; chunk < 4; chunk++) {
        __syncthreads();
        const float4* isrc =
            (const float4*)(g_c1 + (size_t)b * (32 * C1_IC) + chunk * 8 * C1_IC);
        for (int i = t; i < 2480; i += 256) ((float4*)s_in)[i] = isrc[i];
        // weights: rows [chunk*72, chunk*72+72), cols [half*32, half*32+32)
        for (int i = t; i < 72 * 8; i += 256) {
            int rr = i >> 3, c4 = i & 7;
            ((float4*)s_w)[rr * 8 + c4] =
                *(const float4*)(g_wt2 + (chunk * 72 + rr) * 64 + half * 32 + c4 * 4);
        }
        __syncthreads();
        if (active) {
            for (int icl = 0; icl < 8; icl++) {
#pragma unroll
                for (int ky = 0; ky < 3; ky++) {
                    const float* base = s_in + icl * C1_IC + (2 * row + ky) * C1_ROW;
                    float4 ef = *(const float4*)(base + 4 * q);
                    float4 of = *(const float4*)(base + 16 + 4 * q);
                    float  e4 = base[4 * q + 4];
                    int r0 = (icl * 9 + ky * 3) << 5;
                    const float4* wp0 = (const float4*)(s_w + r0 + ocl);
                    const float4* wp1 = (const float4*)(s_w + r0 + 32 + ocl);
                    const float4* wp2 = (const float4*)(s_w + r0 + 64 + ocl);
                    fma8x4(acc, ef.x, ef.y, ef.z, ef.w, wp0[0], wp0[1]);
                    fma8x4(acc, of.x, of.y, of.z, of.w, wp1[0], wp1[1]);
                    fma8x4(acc, ef.y, ef.z, ef.w, e4,   wp2[0], wp2[1]);
                }
            }
        }
    }
    if (active) {
#pragma unroll
        for (int j = 0; j < 8; j++) {
            float* o = g_c2 + ((size_t)b * 64 + oc0 + j) * C2_IC + row * C2_ROW;
#pragma unroll
            for (int l = 0; l < 4; l++) {
                int px = 4 * q + l;
                if (px < 15)
                    o[((px & 1) << 3) + (px >> 1)] = leaky(acc[j * 4 + l]);
            }
        }
    }
}

// ---------------- conv3: 64ch 15x15 -> 128ch 7x7 -> feat --------------------
// One block per b, all 128 oc; input AND weights streamed in 8 chunks of 8 ic.
// smem 46.5 KB -> 3 blocks/SM (24 warps).
__global__ void __launch_bounds__(256, 3) k_conv3(const float* __restrict__ bias) {
    extern __shared__ float sm[];
    float* s_in = sm;                     // 8 * 300 = 2400 fl
    float* s_w  = sm + 2400;              // 8*9*128 = 9216 fl
    int b = blockIdx.x, t = threadIdx.x;

    int ocg = t >> 4;                     // 16 groups of 8 oc
    int oc0 = ocg << 3;
    int pxg = t & 15;                     // 7 rows x 2 quads = 14 active
    int row = pxg >> 1, q = pxg & 1;
    bool active = pxg < 14;

    float acc[32];
#pragma unroll
    for (int j = 0; j < 8; j++) {
        float bv = __ldg(&bias[oc0 + j]);
        acc[j * 4] = bv; acc[j * 4 + 1] = bv;
        acc[j * 4 + 2] = bv; acc[j * 4 + 3] = bv;
    }

    for (int chunk = 0; chunk < 8; chunk++) {
        __syncthreads();
        const float4* isrc =
            (const float4*)(g_c2 + (size_t)b * (64 * C2_IC) + chunk * 8 * C2_IC);
        for (int i = t; i < 600; i += 256) ((float4*)s_in)[i] = isrc[i];
        const float4* wsrc = (const float4*)g_wt3 + chunk * 2304;
        for (int i = t; i < 2304; i += 256) ((float4*)s_w)[i] = wsrc[i];
        __syncthreads();
        if (active) {
            for (int icl = 0; icl < 8; icl++) {
#pragma unroll
                for (int ky = 0; ky < 3; ky++) {
                    const float* base = s_in + icl * C2_IC + (2 * row + ky) * C2_ROW;
                    float4 ef = *(const float4*)(base + 4 * q);
                    float4 of = *(const float4*)(base + 8 + 4 * q);
                    float  e4 = base[4 * q + 4];
                    int r0 = (icl * 9 + ky * 3) << 7;
                    const float4* wp0 = (const float4*)(s_w + r0 + oc0);
                    const float4* wp1 = (const float4*)(s_w + r0 + 128 + oc0);
                    const float4* wp2 = (const float4*)(s_w + r0 + 256 + oc0);
                    fma8x4(acc, ef.x, ef.y, ef.z, ef.w, wp0[0], wp0[1]);
                    fma8x4(acc, of.x, of.y, of.z, of.w, wp1[0], wp1[1]);
                    fma8x4(acc, ef.y, ef.z, ef.w, e4,   wp2[0], wp2[1]);
                }
            }
        }
    }
    if (active) {
#pragma unroll
        for (int j = 0; j < 8; j++) {
            float* o = g_feat + (size_t)b * 6272 + (oc0 + j) * 49 + row * 7;
#pragma unroll
            for (int l = 0; l < 4; l++) {
                int px = 4 * q + l;
                if (px < 7) o[px] = leaky(acc[j * 4 + l]);
            }
        }
    }
}

// ---------------- fused dual-head GEMM (split-K, 8x4 reg tiles) -------------
__global__ void __launch_bounds__(256) k_gemm(
    const float* __restrict__ Ac, const float* __restrict__ Ar,
    const float* __restrict__ Bc, const float* __restrict__ Br,
    float* __restrict__ part, int K, int Ksplit) {
    __shared__ float sA[16 * 128];        // [k][m]
    __shared__ float sB[16 * 64];         // [k][n]
    int head = blockIdx.y >> 2;
    int m0 = blockIdx.x * 128, n0 = (blockIdx.y & 3) * 64;
    int k0 = blockIdx.z * Ksplit;
    const float* A  = head ? Ar : Ac;
    const float* Bw = head ? Br : Bc;
    int t = threadIdx.x;                  // 256
    int a_m = t >> 1, a_f = (t & 1) * 2;            // 2 float4 per thread (A)
    int b_n = t >> 2, b_f = t & 3;                  // 1 float4 per thread (B)
    const float* Ap = A + (size_t)(m0 + a_m) * K + k0;
    const float* Bp = Bw + (size_t)(n0 + b_n) * K + k0;
    int tm = t >> 4, tn = t & 15;
    float acc[32];
#pragma unroll
    for (int i = 0; i < 32; i++) acc[i] = 0.f;
    for (int kk = 0; kk < Ksplit; kk += 16) {
        float4 av0 = *(const float4*)(Ap + kk + a_f * 4);
        float4 av1 = *(const float4*)(Ap + kk + a_f * 4 + 4);
        float4 bv  = *(const float4*)(Bp + kk + b_f * 4);
        __syncthreads();
        sA[(a_f * 4 + 0) * 128 + a_m] = av0.x;
        sA[(a_f * 4 + 1) * 128 + a_m] = av0.y;
        sA[(a_f * 4 + 2) * 128 + a_m] = av0.z;
        sA[(a_f * 4 + 3) * 128 + a_m] = av0.w;
        sA[(a_f * 4 + 4) * 128 + a_m] = av1.x;
        sA[(a_f * 4 + 5) * 128 + a_m] = av1.y;
        sA[(a_f * 4 + 6) * 128 + a_m] = av1.z;
        sA[(a_f * 4 + 7) * 128 + a_m] = av1.w;
        sB[(b_f * 4 + 0) * 64 + b_n] = bv.x;
        sB[(b_f * 4 + 1) * 64 + b_n] = bv.y;
        sB[(b_f * 4 + 2) * 64 + b_n] = bv.z;
        sB[(b_f * 4 + 3) * 64 + b_n] = bv.w;
        __syncthreads();
#pragma unroll
        for (int k = 0; k < 16; k++) {
            float4 a0 = *(const float4*)&sA[k * 128 + tm * 8];
            float4 a1 = *(const float4*)&sA[k * 128 + tm * 8 + 4];
            float4 bq = *(const float4*)&sB[k * 64 + tn * 4];
            float a_[8] = {a0.x, a0.y, a0.z, a0.w, a1.x, a1.y, a1.z, a1.w};
#pragma unroll
            for (int i = 0; i < 8; i++) {
                acc[i * 4 + 0] = fmaf(a_[i], bq.x, acc[i * 4 + 0]);
                acc[i * 4 + 1] = fmaf(a_[i], bq.y, acc[i * 4 + 1]);
                acc[i * 4 + 2] = fmaf(a_[i], bq.z, acc[i * 4 + 2]);
                acc[i * 4 + 3] = fmaf(a_[i], bq.w, acc[i * 4 + 3]);
            }
        }
    }
    float* p = part + (size_t)(blockIdx.z * 2 + head) * (512 * 256);
#pragma unroll
    for (int i = 0; i < 8; i++) {
        float4* rowp = (float4*)(p + (size_t)(m0 + tm * 8 + i) * 256 + n0 + tn * 4);
        *rowp = make_float4(acc[i * 4], acc[i * 4 + 1], acc[i * 4 + 2], acc[i * 4 + 3]);
    }
}

// ---------------- split-K reduce + bias + relu (both heads) -----------------
__global__ void k_reduce(const float* __restrict__ part,
                         const float* __restrict__ cb, const float* __restrict__ rb,
                         float* __restrict__ out, int S) {
    int i = blockIdx.x * 256 + threadIdx.x;        // over 2*512*256
    int head = i >> 17;
    int j = i & 131071;
    float v = 0.f;
    for (int s = 0; s < S; s++) v += part[(size_t)(s * 2 + head) * 131072 + j];
    v += (head ? rb : cb)[j & 255];
    out[i] = fmaxf(v, 0.f);
}

// ---------------- final heads ----------------------------------------------
__global__ void k_fc3(const float* __restrict__ cw, const float* __restrict__ cb,
                      const float* __restrict__ rw, const float* __restrict__ rb,
                      float* __restrict__ out) {
    __shared__ float hc[256], hr[256];
    int b = blockIdx.x, t = threadIdx.x;           // 64 threads
    for (int i = t; i < 256; i += 64) {
        hc[i] = g_h2[b * 256 + i];
        hr[i] = g_h2[131072 + b * 256 + i];
    }
    __syncthreads();
    if (t >= 47) return;
    const float* w = (t == 0) ? cw : rw + (t - 1) * 256;
    const float* h = (t == 0) ? hc : hr;
    float acc = (t == 0) ? cb[0] : rb[t - 1];
    for (int k = 0; k < 256; k++) acc = fmaf(h[k], w[k], acc);
    if (t == 0) out[b] = acc;
    else        out[512 + b * 46 + (t - 1)] = acc;
}

// ---------------- launch ----------------------------------------------------
extern "C" void kernel_launch(void* const* d_in, const int* in_sizes, int n_in,
                              void* d_out, int out_size) {
    const float* pts = (const float*)d_in[0];
    const float* rot = (const float*)d_in[1];
    const float* w1  = (const float*)d_in[2];  const float* b1  = (const float*)d_in[3];
    const float* w2  = (const float*)d_in[4];  const float* b2  = (const float*)d_in[5];
    const float* w3  = (const float*)d_in[6];  const float* b3  = (const float*)d_in[7];
    const float* cw1 = (const float*)d_in[8];  const float* cb1 = (const float*)d_in[9];
    const float* cw2 = (const float*)d_in[10]; const float* cb2 = (const float*)d_in[11];
    const float* cw3 = (const float*)d_in[12]; const float* cb3 = (const float*)d_in[13];
    const float* rw1 = (const float*)d_in[14]; const float* rb1 = (const float*)d_in[15];
    const float* rw2 = (const float*)d_in[16]; const float* rb2 = (const float*)d_in[17];
    const float* rw3 = (const float*)d_in[18]; const float* rb3 = (const float*)d_in[19];
    float* out = (float*)d_out;

    float *featp, *h1p, *h2p, *partp;
    cudaGetSymbolAddress((void**)&featp, g_feat);
    cudaGetSymbolAddress((void**)&h1p, g_h1);
    cudaGetSymbolAddress((void**)&h2p, g_h2);
    cudaGetSymbolAddress((void**)&partp, g_part);

    const int SM1 = (49152 + 3456 + 1536 + 128) * 4;   // 217,088 B
    const int SM2 = (9920 + 2304) * 4;                 // 48,896 B
    const int SM3 = (2400 + 9216) * 4;                 // 46,464 B
    cudaFuncSetAttribute(k_fuse1, cudaFuncAttributeMaxDynamicSharedMemorySize, SM1);
    cudaFuncSetAttribute(k_conv2, cudaFuncAttributeMaxDynamicSharedMemorySize, SM2);
    cudaFuncSetAttribute(k_conv3, cudaFuncAttributeMaxDynamicSharedMemorySize, SM3);

    k_prep<<<(3456 + 18432 + 73728 + 255) / 256, 256>>>(w1, w2, w3);
    k_fuse1<<<BATCH, 512, SM1>>>(pts, rot, b1);
    k_conv2<<<dim3(BATCH, 2), 256, SM2>>>(b2);
    k_conv3<<<BATCH, 256, SM3>>>(b3);
    k_gemm<<<dim3(4, 8, 14), 256>>>(featp, featp, cw1, rw1, partp, 6272, 448);
    k_reduce<<<1024, 256>>>(partp, cb1, rb1, h1p, 14);
    k_gemm<<<dim3(4, 8, 2), 256>>>(h1p, h1p + 131072, cw2, rw2, partp, 256, 128);
    k_reduce<<<1024, 256>>>(partp, cb2, rb2, h2p, 2);
    k_fc3<<<BATCH, 64>>>(cw3, cb3, rw3, rb3, out);
    (void)in_sizes; (void)n_in; (void)out_size;
}

// round 13
// speedup vs baseline: 2.3215x; 1.0325x over previous
#include <cuda_runtime.h>
#include <cuda_bf16.h>

#define BATCH 512
#define NPTS  512
#define NROT  12
#define IMG   64

// padded strides (bank-conflict-free for stride-2 quad reads)
#define C1_ROW 40
#define C1_IC  1240               // 31 * 40
#define C2_ROW 20
#define C2_IC  300                // 15 * 20

// ---------------- scratch (device globals; no allocations allowed) ----------
__device__ float g_c1[BATCH * 32 * C1_IC];            // 81 MB
__device__ float g_c2[BATCH * 64 * C2_IC];            // 39.3 MB
__device__ float g_feat[BATCH * 6272];                // 12.8 MB
__device__ float g_h1[2 * BATCH * 256];
__device__ float g_h2[2 * BATCH * 256];
__device__ float g_part[28 * BATCH * 256];            // [split*2+head][b][n]
__device__ float g_wt1[108 * 32];                     // [r][oc]
__device__ float g_wt2[288 * 64];                     // [r][oc]
// conv3 weights as bf16 hi/lo, plain [oc][576]
__device__ __align__(16) __nv_bfloat16 g_w3h[128 * 576];
__device__ __align__(16) __nv_bfloat16 g_w3l[128 * 576];

__device__ __forceinline__ float leaky(float v) {
    return v >= 0.f ? v : 0.2f * v;
}

// 8 oc x 4 px outer-product FMA block
__device__ __forceinline__ void fma8x4(float* acc, float v0, float v1,
                                       float v2, float v3,
                                       float4 w0, float4 w1) {
    float w[8] = {w0.x, w0.y, w0.z, w0.w, w1.x, w1.y, w1.z, w1.w};
#pragma unroll
    for (int j = 0; j < 8; j++) {
        acc[j * 4 + 0] = fmaf(v0, w[j], acc[j * 4 + 0]);
        acc[j * 4 + 1] = fmaf(v1, w[j], acc[j * 4 + 1]);
        acc[j * 4 + 2] = fmaf(v2, w[j], acc[j * 4 + 2]);
        acc[j * 4 + 3] = fmaf(v3, w[j], acc[j * 4 + 3]);
    }
}

// bf16 m16n8k16 warp MMA (baseline PTX, legal on sm_100)
__device__ __forceinline__ void mma16816(float* d,
                                         unsigned a0, unsigned a1,
                                         unsigned a2, unsigned a3,
                                         unsigned b0, unsigned b1) {
    asm volatile(
        "mma.sync.aligned.m16n8k16.row.col.f32.bf16.bf16.f32 "
        "{%0,%1,%2,%3}, {%4,%5,%6,%7}, {%8,%9}, {%0,%1,%2,%3};"
        : "+f"(d[0]), "+f"(d[1]), "+f"(d[2]), "+f"(d[3])
        : "r"(a0), "r"(a1), "r"(a2), "r"(a3), "r"(b0), "r"(b1));
}

// ---------------- weight prep --------------------------------------------
__global__ void k_prep(const float* __restrict__ w1, const float* __restrict__ w2,
                       const float* __restrict__ w3) {
    int i = blockIdx.x * 256 + threadIdx.x;
    if (i < 3456) {
        int r = i >> 5, oc = i & 31;
        g_wt1[i] = w1[oc * 108 + r];
        return;
    }
    i -= 3456;
    if (i < 18432) {
        int r = i >> 6, oc = i & 63;
        g_wt2[i] = w2[oc * 288 + r];
        return;
    }
    i -= 18432;
    if (i < 73728) {
        float v = w3[i];              // [oc][576] row-major, identity layout
        __nv_bfloat16 h = __float2bfloat16(v);
        __nv_bfloat16 l = __float2bfloat16(v - __bfloat162float(h));
        g_w3h[i] = h;
        g_w3l[i] = l;
    }
}

// ---------------- fused scatter + conv1 (per-batch block) -------------------
__global__ void __launch_bounds__(512, 1) k_fuse1(
    const float* __restrict__ pts, const float* __restrict__ rot,
    const float* __restrict__ bias) {
    extern __shared__ float sm[];
    float* s_img = sm;                    // 49152 floats (12 x 64 x 64 deint-x)
    float* s_w   = sm + 49152;            // 3456
    float* s_pts = s_w + 3456;            // 1536
    float* s_rot = s_pts + 1536;          // 108
    unsigned int* u_img = (unsigned int*)s_img;
    int b = blockIdx.x, t = threadIdx.x;

    for (int i = t; i < 49152 / 4; i += 512)
        ((uint4*)u_img)[i] = make_uint4(0u, 0u, 0u, 0u);
    for (int i = t; i < 1536; i += 512) s_pts[i] = pts[b * 1536 + i];
    if (t < 108) s_rot[t] = rot[t];
    for (int i = t; i < 3456 / 4; i += 512)
        ((float4*)s_w)[i] = ((const float4*)g_wt1)[i];
    __syncthreads();

    // scatter: key = (n<<23) | (valbits>>9); atomicMax => last point index wins
    for (int task = t; task < NROT * NPTS; task += 512) {
        int m = task >> 9, n = task & 511;
        float x = s_pts[n * 3], y = s_pts[n * 3 + 1], z = s_pts[n * 3 + 2];
        const float* r = s_rot + m * 9;
        float xr = r[0] * x + r[1] * y + r[2] * z;
        float zr = r[6] * x + r[7] * y + r[8] * z;
        float fx = rintf((xr + 2.0f) / 0.0625f);   // round-half-even == jnp.round
        float fy = rintf((y + 2.0f) / 0.0625f);
        int px = (int)fx, py = (int)fy;
        bool ok = (px >= 0) && (px < IMG) && (py >= 0) && (py < IMG);
        if (!ok) { px = 0; py = 0; }               // proj*ok -> OOB hits (0,0)
        float val = zr / 10.0f;
        unsigned int key = ((unsigned int)n << 23) | (__float_as_uint(val) >> 9);
        int didx = ((px & 1) << 5) + (px >> 1);    // deinterleave x
        atomicMax(&u_img[(m << 12) + (py << 6) + didx], key);
    }
    __syncthreads();
    for (int i = t; i < 49152 / 4; i += 512) {
        uint4 v = ((uint4*)u_img)[i];
        v.x = (v.x & 0x7fffffu) << 9; v.y = (v.y & 0x7fffffu) << 9;
        v.z = (v.z & 0x7fffffu) << 9; v.w = (v.w & 0x7fffffu) << 9;
        ((uint4*)u_img)[i] = v;                    // decode to float bits
    }
    __syncthreads();

    // conv1: 12ch 64x64 -> 32ch 31x31 stride-2 leaky.
    int pxg = t & 255;
    int row = pxg >> 3, q = pxg & 7;
    bool active = pxg < 248;                        // 31 rows x 8 quads
#pragma unroll
    for (int uu = 0; uu < 2; uu++) {
        int ocg = (t >> 8) + 2 * uu;                // 0..3
        int oc0 = ocg << 3;
        if (active) {
            float acc[32];
#pragma unroll
            for (int j = 0; j < 8; j++) {
                float bv = __ldg(&bias[oc0 + j]);
                acc[j * 4] = bv; acc[j * 4 + 1] = bv;
                acc[j * 4 + 2] = bv; acc[j * 4 + 3] = bv;
            }
            for (int ic = 0; ic < NROT; ic++) {
#pragma unroll
                for (int ky = 0; ky < 3; ky++) {
                    const float* base = s_img + (ic << 12) + ((2 * row + ky) << 6);
                    float4 ef = *(const float4*)(base + 4 * q);
                    float4 of = *(const float4*)(base + 32 + 4 * q);
                    float  e4 = base[4 * q + 4];
                    int r0 = (ic * 9 + ky * 3) << 5;
                    const float4* wp0 = (const float4*)(s_w + r0 + oc0);
                    const float4* wp1 = (const float4*)(s_w + r0 + 32 + oc0);
                    const float4* wp2 = (const float4*)(s_w + r0 + 64 + oc0);
                    fma8x4(acc, ef.x, ef.y, ef.z, ef.w, wp0[0], wp0[1]);
                    fma8x4(acc, of.x, of.y, of.z, of.w, wp1[0], wp1[1]);
                    fma8x4(acc, ef.y, ef.z, ef.w, e4,   wp2[0], wp2[1]);
                }
            }
#pragma unroll
            for (int j = 0; j < 8; j++) {
                float* o = g_c1 + ((size_t)b * 32 + oc0 + j) * C1_IC + row * C1_ROW;
#pragma unroll
                for (int l = 0; l < 4; l++) {
                    int px = 4 * q + l;
                    if (px < 31)
                        o[((px & 1) << 4) + (px >> 1)] = leaky(acc[j * 4 + l]);
                }
            }
        }
    }
}

// ---------------- conv2: 32ch 31x31 -> 64ch 15x15 ---------------------------
__global__ void __launch_bounds__(256, 3) k_conv2(const float* __restrict__ bias) {
    extern __shared__ float sm[];
    float* s_in = sm;                     // 8 * 1240 = 9920 fl
    float* s_w  = sm + 9920;              // 8*9*32 = 2304 fl
    int b = blockIdx.x, half = blockIdx.y, t = threadIdx.x;

    int ocg = t >> 6;                     // 4 groups of 8 oc
    int ocl = ocg << 3;                   // local oc in half
    int oc0 = half * 32 + ocl;
    int pxg = t & 63;                     // 15 rows x 4 quads = 60 active
    int row = pxg >> 2, q = pxg & 3;
    bool active = pxg < 60;
    float acc[32];
#pragma unroll
    for (int j = 0; j < 8; j++) {
        float bv = __ldg(&bias[oc0 + j]);
        acc[j * 4] = bv; acc[j * 4 + 1] = bv;
        acc[j * 4 + 2] = bv; acc[j * 4 + 3] = bv;
    }
    for (int chunk = 0; chunk < 4; chunk++) {
        __syncthreads();
        const float4* isrc =
            (const float4*)(g_c1 + (size_t)b * (32 * C1_IC) + chunk * 8 * C1_IC);
        for (int i = t; i < 2480; i += 256) ((float4*)s_in)[i] = isrc[i];
        for (int i = t; i < 72 * 8; i += 256) {
            int rr = i >> 3, c4 = i & 7;
            ((float4*)s_w)[rr * 8 + c4] =
                *(const float4*)(g_wt2 + (chunk * 72 + rr) * 64 + half * 32 + c4 * 4);
        }
        __syncthreads();
        if (active) {
            for (int icl = 0; icl < 8; icl++) {
#pragma unroll
                for (int ky = 0; ky < 3; ky++) {
                    const float* base = s_in + icl * C1_IC + (2 * row + ky) * C1_ROW;
                    float4 ef = *(const float4*)(base + 4 * q);
                    float4 of = *(const float4*)(base + 16 + 4 * q);
                    float  e4 = base[4 * q + 4];
                    int r0 = (icl * 9 + ky * 3) << 5;
                    const float4* wp0 = (const float4*)(s_w + r0 + ocl);
                    const float4* wp1 = (const float4*)(s_w + r0 + 32 + ocl);
                    const float4* wp2 = (const float4*)(s_w + r0 + 64 + ocl);
                    fma8x4(acc, ef.x, ef.y, ef.z, ef.w, wp0[0], wp0[1]);
                    fma8x4(acc, of.x, of.y, of.z, of.w, wp1[0], wp1[1]);
                    fma8x4(acc, ef.y, ef.z, ef.w, e4,   wp2[0], wp2[1]);
                }
            }
        }
    }
    if (active) {
#pragma unroll
        for (int j = 0; j < 8; j++) {
            float* o = g_c2 + ((size_t)b * 64 + oc0 + j) * C2_IC + row * C2_ROW;
#pragma unroll
            for (int l = 0; l < 4; l++) {
                int px = 4 * q + l;
                if (px < 15)
                    o[((px & 1) << 3) + (px >> 1)] = leaky(acc[j * 4 + l]);
            }
        }
    }
}

// ---------------- conv3 via mma.sync bf16 hi/lo ------------------------------
// Per batch: D[128 oc, 56 px(pad)] = W[128,576] * im2col[576,56]
// smem (bf16 units): Ah[128*72]@0, Al@9216, Bh[56*72]@18432, Bl@22464
// total 26496 bf16 = 52992 B -> 4 blocks/SM.
#define A_STR 72
__global__ void __launch_bounds__(128) k_conv3_mma(const float* __restrict__ bias) {
    extern __shared__ __nv_bfloat16 smb[];
    __nv_bfloat16* Ah = smb;
    __nv_bfloat16* Al = smb + 9216;
    __nv_bfloat16* Bh = smb + 18432;
    __nv_bfloat16* Bl = smb + 22464;
    int b = blockIdx.x, t = threadIdx.x;
    int wid = t >> 5, lane = t & 31;
    int r = lane >> 2, cp = (lane & 3) * 2;

    const float* X = g_c2 + (size_t)b * (64 * C2_IC);
    float facc[2][7][4];
#pragma unroll
    for (int mt = 0; mt < 2; mt++)
#pragma unroll
        for (int nt = 0; nt < 7; nt++)
#pragma unroll
            for (int j = 0; j < 4; j++) facc[mt][nt][j] = 0.f;

    for (int c = 0; c < 9; c++) {
        __syncthreads();
        // copy A chunk: [128 oc][64 k] hi/lo (uint4 = 8 bf16)
        for (int i = t; i < 1024; i += 128) {
            int row = i >> 3, seg = i & 7;
            *(uint4*)(Ah + row * A_STR + seg * 8) =
                ((const uint4*)g_w3h)[row * 72 + c * 8 + seg];
            *(uint4*)(Al + row * A_STR + seg * 8) =
                ((const uint4*)g_w3l)[row * 72 + c * 8 + seg];
        }
        // build B chunk: im2col [56 n][64 k] hi/lo (rows 49..55 zero)
        for (int i = t; i < 3584; i += 128) {
            int n = i >> 6, j = i & 63;
            float v = 0.f;
            if (n < 49) {
                int k = c * 64 + j;
                int ic = k / 9, r9 = k - ic * 9;
                int ky = r9 / 3, kx = r9 - ky * 3;
                int prow = n / 7, pcol = n - prow * 7;
                int iy = 2 * prow + ky, ix = 2 * pcol + kx;
                v = __ldg(&X[ic * C2_IC + iy * C2_ROW + ((ix & 1) << 3) + (ix >> 1)]);
            }
            __nv_bfloat16 h = __float2bfloat16(v);
            __nv_bfloat16 l = __float2bfloat16(v - __bfloat162float(h));
            Bh[n * A_STR + j] = h;
            Bl[n * A_STR + j] = l;
        }
        __syncthreads();
#pragma unroll
        for (int ks = 0; ks < 4; ks++) {
            int k0 = ks * 16;
            unsigned ah[2][4], al[2][4];
#pragma unroll
            for (int mt = 0; mt < 2; mt++) {
                int row0 = wid * 32 + mt * 16 + r;
                ah[mt][0] = *(const unsigned*)(Ah + row0 * A_STR + k0 + cp);
                ah[mt][1] = *(const unsigned*)(Ah + (row0 + 8) * A_STR + k0 + cp);
                ah[mt][2] = *(const unsigned*)(Ah + row0 * A_STR + k0 + 8 + cp);
                ah[mt][3] = *(const unsigned*)(Ah + (row0 + 8) * A_STR + k0 + 8 + cp);
                al[mt][0] = *(const unsigned*)(Al + row0 * A_STR + k0 + cp);
                al[mt][1] = *(const unsigned*)(Al + (row0 + 8) * A_STR + k0 + cp);
                al[mt][2] = *(const unsigned*)(Al + row0 * A_STR + k0 + 8 + cp);
                al[mt][3] = *(const unsigned*)(Al + (row0 + 8) * A_STR + k0 + 8 + cp);
            }
#pragma unroll
            for (int nt = 0; nt < 7; nt++) {
                int n = nt * 8 + r;
                unsigned bh0 = *(const unsigned*)(Bh + n * A_STR + k0 + cp);
                unsigned bh1 = *(const unsigned*)(Bh + n * A_STR + k0 + 8 + cp);
                unsigned bl0 = *(const unsigned*)(Bl + n * A_STR + k0 + cp);
                unsigned bl1 = *(const unsigned*)(Bl + n * A_STR + k0 + 8 + cp);
#pragma unroll
                for (int mt = 0; mt < 2; mt++) {
                    mma16816(facc[mt][nt], ah[mt][0], ah[mt][1], ah[mt][2], ah[mt][3], bh0, bh1);
                    mma16816(facc[mt][nt], ah[mt][0], ah[mt][1], ah[mt][2], ah[mt][3], bl0, bl1);
                    mma16816(facc[mt][nt], al[mt][0], al[mt][1], al[mt][2], al[mt][3], bh0, bh1);
                }
            }
        }
    }
    // epilogue: bias + leaky + store to g_feat [oc][49]
    float* o = g_feat + (size_t)b * 6272;
#pragma unroll
    for (int mt = 0; mt < 2; mt++) {
        int oc0 = wid * 32 + mt * 16 + r;
        float bv0 = __ldg(&bias[oc0]);
        float bv8 = __ldg(&bias[oc0 + 8]);
#pragma unroll
        for (int nt = 0; nt < 7; nt++) {
            int px = nt * 8 + cp;
            if (px < 49) {
                o[oc0 * 49 + px] = leaky(facc[mt][nt][0] + bv0);
                o[(oc0 + 8) * 49 + px] = leaky(facc[mt][nt][2] + bv8);
            }
            if (px + 1 < 49) {
                o[oc0 * 49 + px + 1] = leaky(facc[mt][nt][1] + bv0);
                o[(oc0 + 8) * 49 + px + 1] = leaky(facc[mt][nt][3] + bv8);
            }
        }
    }
}

// ---------------- fused dual-head GEMM (split-K, 8x4 reg tiles) -------------
__global__ void __launch_bounds__(256) k_gemm(
    const float* __restrict__ Ac, const float* __restrict__ Ar,
    const float* __restrict__ Bc, const float* __restrict__ Br,
    float* __restrict__ part, int K, int Ksplit) {
    __shared__ float sA[16 * 128];        // [k][m]
    __shared__ float sB[16 * 64];         // [k][n]
    int head = blockIdx.y >> 2;
    int m0 = blockIdx.x * 128, n0 = (blockIdx.y & 3) * 64;
    int k0 = blockIdx.z * Ksplit;
    const float* A  = head ? Ar : Ac;
    const float* Bw = head ? Br : Bc;
    int t = threadIdx.x;                  // 256
    int a_m = t >> 1, a_f = (t & 1) * 2;            // 2 float4 per thread (A)
    int b_n = t >> 2, b_f = t & 3;                  // 1 float4 per thread (B)
    const float* Ap = A + (size_t)(m0 + a_m) * K + k0;
    const float* Bp = Bw + (size_t)(n0 + b_n) * K + k0;
    int tm = t >> 4, tn = t & 15;
    float acc[32];
#pragma unroll
    for (int i = 0; i < 32; i++) acc[i] = 0.f;
    for (int kk = 0; kk < Ksplit; kk += 16) {
        float4 av0 = *(const float4*)(Ap + kk + a_f * 4);
        float4 av1 = *(const float4*)(Ap + kk + a_f * 4 + 4);
        float4 bv  = *(const float4*)(Bp + kk + b_f * 4);
        __syncthreads();
        sA[(a_f * 4 + 0) * 128 + a_m] = av0.x;
        sA[(a_f * 4 + 1) * 128 + a_m] = av0.y;
        sA[(a_f * 4 + 2) * 128 + a_m] = av0.z;
        sA[(a_f * 4 + 3) * 128 + a_m] = av0.w;
        sA[(a_f * 4 + 4) * 128 + a_m] = av1.x;
        sA[(a_f * 4 + 5) * 128 + a_m] = av1.y;
        sA[(a_f * 4 + 6) * 128 + a_m] = av1.z;
        sA[(a_f * 4 + 7) * 128 + a_m] = av1.w;
        sB[(b_f * 4 + 0) * 64 + b_n] = bv.x;
        sB[(b_f * 4 + 1) * 64 + b_n] = bv.y;
        sB[(b_f * 4 + 2) * 64 + b_n] = bv.z;
        sB[(b_f * 4 + 3) * 64 + b_n] = bv.w;
        __syncthreads();
#pragma unroll
        for (int k = 0; k < 16; k++) {
            float4 a0 = *(const float4*)&sA[k * 128 + tm * 8];
            float4 a1 = *(const float4*)&sA[k * 128 + tm * 8 + 4];
            float4 bq = *(const float4*)&sB[k * 64 + tn * 4];
            float a_[8] = {a0.x, a0.y, a0.z, a0.w, a1.x, a1.y, a1.z, a1.w};
#pragma unroll
            for (int i = 0; i < 8; i++) {
                acc[i * 4 + 0] = fmaf(a_[i], bq.x, acc[i * 4 + 0]);
                acc[i * 4 + 1] = fmaf(a_[i], bq.y, acc[i * 4 + 1]);
                acc[i * 4 + 2] = fmaf(a_[i], bq.z, acc[i * 4 + 2]);
                acc[i * 4 + 3] = fmaf(a_[i], bq.w, acc[i * 4 + 3]);
            }
        }
    }
    float* p = part + (size_t)(blockIdx.z * 2 + head) * (512 * 256);
#pragma unroll
    for (int i = 0; i < 8; i++) {
        float4* rowp = (float4*)(p + (size_t)(m0 + tm * 8 + i) * 256 + n0 + tn * 4);
        *rowp = make_float4(acc[i * 4], acc[i * 4 + 1], acc[i * 4 + 2], acc[i * 4 + 3]);
    }
}

// ---------------- split-K reduce + bias + relu (both heads) -----------------
__global__ void k_reduce(const float* __restrict__ part,
                         const float* __restrict__ cb, const float* __restrict__ rb,
                         float* __restrict__ out, int S) {
    int i = blockIdx.x * 256 + threadIdx.x;        // over 2*512*256
    int head = i >> 17;
    int j = i & 131071;
    float v = 0.f;
    for (int s = 0; s < S; s++) v += part[(size_t)(s * 2 + head) * 131072 + j];
    v += (head ? rb : cb)[j & 255];
    out[i] = fmaxf(v, 0.f);
}

// ---------------- final heads ----------------------------------------------
__global__ void k_fc3(const float* __restrict__ cw, const float* __restrict__ cb,
                      const float* __restrict__ rw, const float* __restrict__ rb,
                      float* __restrict__ out) {
    __shared__ float hc[256], hr[256];
    int b = blockIdx.x, t = threadIdx.x;           // 64 threads
    for (int i = t; i < 256; i += 64) {
        hc[i] = g_h2[b * 256 + i];
        hr[i] = g_h2[131072 + b * 256 + i];
    }
    __syncthreads();
    if (t >= 47) return;
    const float* w = (t == 0) ? cw : rw + (t - 1) * 256;
    const float* h = (t == 0) ? hc : hr;
    float acc = (t == 0) ? cb[0] : rb[t - 1];
    for (int k = 0; k < 256; k++) acc = fmaf(h[k], w[k], acc);
    if (t == 0) out[b] = acc;
    else        out[512 + b * 46 + (t - 1)] = acc;
}

// ---------------- launch ----------------------------------------------------
extern "C" void kernel_launch(void* const* d_in, const int* in_sizes, int n_in,
                              void* d_out, int out_size) {
    const float* pts = (const float*)d_in[0];
    const float* rot = (const float*)d_in[1];
    const float* w1  = (const float*)d_in[2];  const float* b1  = (const float*)d_in[3];
    const float* w2  = (const float*)d_in[4];  const float* b2  = (const float*)d_in[5];
    const float* w3  = (const float*)d_in[6];  const float* b3  = (const float*)d_in[7];
    const float* cw1 = (const float*)d_in[8];  const float* cb1 = (const float*)d_in[9];
    const float* cw2 = (const float*)d_in[10]; const float* cb2 = (const float*)d_in[11];
    const float* cw3 = (const float*)d_in[12]; const float* cb3 = (const float*)d_in[13];
    const float* rw1 = (const float*)d_in[14]; const float* rb1 = (const float*)d_in[15];
    const float* rw2 = (const float*)d_in[16]; const float* rb2 = (const float*)d_in[17];
    const float* rw3 = (const float*)d_in[18]; const float* rb3 = (const float*)d_in[19];
    float* out = (float*)d_out;

    float *featp, *h1p, *h2p, *partp;
    cudaGetSymbolAddress((void**)&featp, g_feat);
    cudaGetSymbolAddress((void**)&h1p, g_h1);
    cudaGetSymbolAddress((void**)&h2p, g_h2);
    cudaGetSymbolAddress((void**)&partp, g_part);

    const int SM1 = (49152 + 3456 + 1536 + 128) * 4;   // 217,088 B
    const int SM2 = (9920 + 2304) * 4;                 // 48,896 B
    const int SM3 = 26496 * 2;                         // 52,992 B (bf16 units)
    cudaFuncSetAttribute(k_fuse1, cudaFuncAttributeMaxDynamicSharedMemorySize, SM1);
    cudaFuncSetAttribute(k_conv2, cudaFuncAttributeMaxDynamicSharedMemorySize, SM2);
    cudaFuncSetAttribute(k_conv3_mma, cudaFuncAttributeMaxDynamicSharedMemorySize, SM3);

    k_prep<<<(3456 + 18432 + 73728 + 255) / 256, 256>>>(w1, w2, w3);
    k_fuse1<<<BATCH, 512, SM1>>>(pts, rot, b1);
    k_conv2<<<dim3(BATCH, 2), 256, SM2>>>(b2);
    k_conv3_mma<<<BATCH, 128, SM3>>>(b3);
    k_gemm<<<dim3(4, 8, 14), 256>>>(featp, featp, cw1, rw1, partp, 6272, 448);
    k_reduce<<<1024, 256>>>(partp, cb1, rb1, h1p, 14);
    k_gemm<<<dim3(4, 8, 2), 256>>>(h1p, h1p + 131072, cw2, rw2, partp, 256, 128);
    k_reduce<<<1024, 256>>>(partp, cb2, rb2, h2p, 2);
    k_fc3<<<BATCH, 64>>>(cw3, cb3, rw3, rb3, out);
    (void)in_sizes; (void)n_in; (void)out_size;
}

// round 15
// speedup vs baseline: 2.5822x; 1.1123x over previous
#include <cuda_runtime.h>
#include <cuda_bf16.h>

#define BATCH 512
#define NPTS  512
#define NROT  12
#define IMG   64

// padded strides (bank-conflict-free for stride-2 quad reads)
#define C1_ROW 40
#define C1_IC  1240               // 31 * 40

// ---------------- scratch (device globals; no allocations allowed) ----------
__device__ float g_c1[BATCH * 32 * C1_IC];            // 81 MB
// conv2 output: bf16 hi/lo, channels-last [b][pix(225)][64]
__device__ __align__(16) __nv_bfloat16 g_c2h[BATCH * 225 * 64];
__device__ __align__(16) __nv_bfloat16 g_c2l[BATCH * 225 * 64];
__device__ float g_feat[BATCH * 6272];                // 12.8 MB
__device__ float g_h1[2 * BATCH * 256];
__device__ float g_h2[2 * BATCH * 256];
__device__ float g_part[28 * BATCH * 256];            // [split*2+head][b][n]
__device__ float g_wt1[108 * 32];                     // [r][oc]
__device__ float g_wt2[288 * 64];                     // [r][oc]
// conv3 weights bf16 hi/lo, [tap(9)][oc(128)][ic(64)]
__device__ __align__(16) __nv_bfloat16 g_w3h[9 * 128 * 64];
__device__ __align__(16) __nv_bfloat16 g_w3l[9 * 128 * 64];

__device__ __forceinline__ float leaky(float v) {
    return v >= 0.f ? v : 0.2f * v;
}

// 8 oc x 4 px outer-product FMA block
__device__ __forceinline__ void fma8x4(float* acc, float v0, float v1,
                                       float v2, float v3,
                                       float4 w0, float4 w1) {
    float w[8] = {w0.x, w0.y, w0.z, w0.w, w1.x, w1.y, w1.z, w1.w};
#pragma unroll
    for (int j = 0; j < 8; j++) {
        acc[j * 4 + 0] = fmaf(v0, w[j], acc[j * 4 + 0]);
        acc[j * 4 + 1] = fmaf(v1, w[j], acc[j * 4 + 1]);
        acc[j * 4 + 2] = fmaf(v2, w[j], acc[j * 4 + 2]);
        acc[j * 4 + 3] = fmaf(v3, w[j], acc[j * 4 + 3]);
    }
}

// bf16 m16n8k16 warp MMA (baseline PTX, legal on sm_100)
__device__ __forceinline__ void mma16816(float* d,
                                         unsigned a0, unsigned a1,
                                         unsigned a2, unsigned a3,
                                         unsigned b0, unsigned b1) {
    asm volatile(
        "mma.sync.aligned.m16n8k16.row.col.f32.bf16.bf16.f32 "
        "{%0,%1,%2,%3}, {%4,%5,%6,%7}, {%8,%9}, {%0,%1,%2,%3};"
        : "+f"(d[0]), "+f"(d[1]), "+f"(d[2]), "+f"(d[3])
        : "r"(a0), "r"(a1), "r"(a2), "r"(a3), "r"(b0), "r"(b1));
}

// ---------------- weight prep --------------------------------------------
__global__ void k_prep(const float* __restrict__ w1, const float* __restrict__ w2,
                       const float* __restrict__ w3) {
    int i = blockIdx.x * 256 + threadIdx.x;
    if (i < 3456) {
        int r = i >> 5, oc = i & 31;
        g_wt1[i] = w1[oc * 108 + r];
        return;
    }
    i -= 3456;
    if (i < 18432) {
        int r = i >> 6, oc = i & 63;
        g_wt2[i] = w2[oc * 288 + r];
        return;
    }
    i -= 18432;
    if (i < 73728) {
        // dst [tap][oc][ic]; src w3[oc][ic*9 + tap]
        int c = i >> 13, e = i & 8191;
        int oc = e >> 6, ic = e & 63;
        float v = w3[oc * 576 + ic * 9 + c];
        __nv_bfloat16 h = __float2bfloat16(v);
        __nv_bfloat16 l = __float2bfloat16(v - __bfloat162float(h));
        g_w3h[i] = h;
        g_w3l[i] = l;
    }
}

// ---------------- fused scatter + conv1 (per-batch block) -------------------
__global__ void __launch_bounds__(512, 1) k_fuse1(
    const float* __restrict__ pts, const float* __restrict__ rot,
    const float* __restrict__ bias) {
    extern __shared__ float sm[];
    float* s_img = sm;                    // 49152 floats (12 x 64 x 64 deint-x)
    float* s_w   = sm + 49152;            // 3456
    float* s_pts = s_w + 3456;            // 1536
    float* s_rot = s_pts + 1536;          // 108
    unsigned int* u_img = (unsigned int*)s_img;
    int b = blockIdx.x, t = threadIdx.x;

    for (int i = t; i < 49152 / 4; i += 512)
        ((uint4*)u_img)[i] = make_uint4(0u, 0u, 0u, 0u);
    for (int i = t; i < 1536; i += 512) s_pts[i] = pts[b * 1536 + i];
    if (t < 108) s_rot[t] = rot[t];
    for (int i = t; i < 3456 / 4; i += 512)
        ((float4*)s_w)[i] = ((const float4*)g_wt1)[i];
    __syncthreads();

    // scatter: key = (n<<23) | (valbits>>9); atomicMax => last point index wins
    for (int task = t; task < NROT * NPTS; task += 512) {
        int m = task >> 9, n = task & 511;
        float x = s_pts[n * 3], y = s_pts[n * 3 + 1], z = s_pts[n * 3 + 2];
        const float* r = s_rot + m * 9;
        float xr = r[0] * x + r[1] * y + r[2] * z;
        float zr = r[6] * x + r[7] * y + r[8] * z;
        float fx = rintf((xr + 2.0f) / 0.0625f);   // round-half-even == jnp.round
        float fy = rintf((y + 2.0f) / 0.0625f);
        int px = (int)fx, py = (int)fy;
        bool ok = (px >= 0) && (px < IMG) && (py >= 0) && (py < IMG);
        if (!ok) { px = 0; py = 0; }               // proj*ok -> OOB hits (0,0)
        float val = zr / 10.0f;
        unsigned int key = ((unsigned int)n << 23) | (__float_as_uint(val) >> 9);
        int didx = ((px & 1) << 5) + (px >> 1);    // deinterleave x
        atomicMax(&u_img[(m << 12) + (py << 6) + didx], key);
    }
    __syncthreads();
    for (int i = t; i < 49152 / 4; i += 512) {
        uint4 v = ((uint4*)u_img)[i];
        v.x = (v.x & 0x7fffffu) << 9; v.y = (v.y & 0x7fffffu) << 9;
        v.z = (v.z & 0x7fffffu) << 9; v.w = (v.w & 0x7fffffu) << 9;
        ((uint4*)u_img)[i] = v;                    // decode to float bits
    }
    __syncthreads();

    // conv1: 12ch 64x64 -> 32ch 31x31 stride-2 leaky.
    int pxg = t & 255;
    int row = pxg >> 3, q = pxg & 7;
    bool active = pxg < 248;                        // 31 rows x 8 quads
#pragma unroll
    for (int uu = 0; uu < 2; uu++) {
        int ocg = (t >> 8) + 2 * uu;                // 0..3
        int oc0 = ocg << 3;
        if (active) {
            float acc[32];
#pragma unroll
            for (int j = 0; j < 8; j++) {
                float bv = __ldg(&bias[oc0 + j]);
                acc[j * 4] = bv; acc[j * 4 + 1] = bv;
                acc[j * 4 + 2] = bv; acc[j * 4 + 3] = bv;
            }
            for (int ic = 0; ic < NROT; ic++) {
#pragma unroll
                for (int ky = 0; ky < 3; ky++) {
                    const float* base = s_img + (ic << 12) + ((2 * row + ky) << 6);
                    float4 ef = *(const float4*)(base + 4 * q);
                    float4 of = *(const float4*)(base + 32 + 4 * q);
                    float  e4 = base[4 * q + 4];
                    int r0 = (ic * 9 + ky * 3) << 5;
                    const float4* wp0 = (const float4*)(s_w + r0 + oc0);
                    const float4* wp1 = (const float4*)(s_w + r0 + 32 + oc0);
                    const float4* wp2 = (const float4*)(s_w + r0 + 64 + oc0);
                    fma8x4(acc, ef.x, ef.y, ef.z, ef.w, wp0[0], wp0[1]);
                    fma8x4(acc, of.x, of.y, of.z, of.w, wp1[0], wp1[1]);
                    fma8x4(acc, ef.y, ef.z, ef.w, e4,   wp2[0], wp2[1]);
                }
            }
#pragma unroll
            for (int j = 0; j < 8; j++) {
                float* o = g_c1 + ((size_t)b * 32 + oc0 + j) * C1_IC + row * C1_ROW;
#pragma unroll
                for (int l = 0; l < 4; l++) {
                    int px = 4 * q + l;
                    if (px < 31)
                        o[((px & 1) << 4) + (px >> 1)] = leaky(acc[j * 4 + l]);
                }
            }
        }
    }
}

// ---------------- conv2: 32ch 31x31 -> 64ch 15x15 ---------------------------
// output: bf16 hi/lo channels-last [b][pix][64]
__global__ void __launch_bounds__(256, 3) k_conv2(const float* __restrict__ bias) {
    extern __shared__ float sm[];
    float* s_in = sm;                     // 8 * 1240 = 9920 fl
    float* s_w  = sm + 9920;              // 8*9*32 = 2304 fl
    int b = blockIdx.x, half = blockIdx.y, t = threadIdx.x;

    int ocg = t >> 6;                     // 4 groups of 8 oc
    int ocl = ocg << 3;                   // local oc in half
    int oc0 = half * 32 + ocl;
    int pxg = t & 63;                     // 15 rows x 4 quads = 60 active
    int row = pxg >> 2, q = pxg & 3;
    bool active = pxg < 60;
    float acc[32];
#pragma unroll
    for (int j = 0; j < 8; j++) {
        float bv = __ldg(&bias[oc0 + j]);
        acc[j * 4] = bv; acc[j * 4 + 1] = bv;
        acc[j * 4 + 2] = bv; acc[j * 4 + 3] = bv;
    }
    for (int chunk = 0; chunk < 4; chunk++) {
        __syncthreads();
        const float4* isrc =
            (const float4*)(g_c1 + (size_t)b * (32 * C1_IC) + chunk * 8 * C1_IC);
        for (int i = t; i < 2480; i += 256) ((float4*)s_in)[i] = isrc[i];
        for (int i = t; i < 72 * 8; i += 256) {
            int rr = i >> 3, c4 = i & 7;
            ((float4*)s_w)[rr * 8 + c4] =
                *(const float4*)(g_wt2 + (chunk * 72 + rr) * 64 + half * 32 + c4 * 4);
        }
        __syncthreads();
        if (active) {
            for (int icl = 0; icl < 8; icl++) {
#pragma unroll
                for (int ky = 0; ky < 3; ky++) {
                    const float* base = s_in + icl * C1_IC + (2 * row + ky) * C1_ROW;
                    float4 ef = *(const float4*)(base + 4 * q);
                    float4 of = *(const float4*)(base + 16 + 4 * q);
                    float  e4 = base[4 * q + 4];
                    int r0 = (icl * 9 + ky * 3) << 5;
                    const float4* wp0 = (const float4*)(s_w + r0 + ocl);
                    const float4* wp1 = (const float4*)(s_w + r0 + 32 + ocl);
                    const float4* wp2 = (const float4*)(s_w + r0 + 64 + ocl);
                    fma8x4(acc, ef.x, ef.y, ef.z, ef.w, wp0[0], wp0[1]);
                    fma8x4(acc, of.x, of.y, of.z, of.w, wp1[0], wp1[1]);
                    fma8x4(acc, ef.y, ef.z, ef.w, e4,   wp2[0], wp2[1]);
                }
            }
        }
    }
    if (active) {
#pragma unroll
        for (int l = 0; l < 4; l++) {
            int px = 4 * q + l;
            if (px < 15) {
                size_t base = ((size_t)b * 225 + row * 15 + px) * 64 + oc0;
#pragma unroll
                for (int j = 0; j < 8; j++) {
                    float v = leaky(acc[j * 4 + l]);
                    __nv_bfloat16 h = __float2bfloat16(v);
                    __nv_bfloat16 lo = __float2bfloat16(v - __bfloat162float(h));
                    g_c2h[base + j] = h;
                    g_c2l[base + j] = lo;
                }
            }
        }
    }
}

// ---------------- conv3 via mma.sync bf16 hi/lo ------------------------------
// Per batch: D[128 oc, 56 px(pad)] = W[128,576] * im2col[576,56]
// K-chunk = one (ky,kx) tap = 64 contiguous channels (channels-last input).
// smem (bf16): Ah[128*72]@0, Al@9216, Bh[56*72]@18432, Bl@22464 -> 52992 B.
#define A_STR 72
__global__ void __launch_bounds__(256) k_conv3_mma(const float* __restrict__ bias) {
    extern __shared__ __nv_bfloat16 smb[];
    __nv_bfloat16* Ah = smb;
    __nv_bfloat16* Al = smb + 9216;
    __nv_bfloat16* Bh = smb + 18432;
    __nv_bfloat16* Bl = smb + 22464;
    int b = blockIdx.x, t = threadIdx.x;
    int wid = t >> 5, lane = t & 31;
    int r = lane >> 2, cp = (lane & 3) * 2;

    const __nv_bfloat16* Xh = g_c2h + (size_t)b * (225 * 64);
    const __nv_bfloat16* Xl = g_c2l + (size_t)b * (225 * 64);
    float facc[7][4];
#pragma unroll
    for (int nt = 0; nt < 7; nt++)
#pragma unroll
        for (int j = 0; j < 4; j++) facc[nt][j] = 0.f;

    for (int c = 0; c < 9; c++) {
        int ky = c / 3, kx = c - 3 * (c / 3);
        __syncthreads();
        // A chunk copy: [128 oc][64 k] hi/lo, 1024 uint4 each
        const uint4* awh = (const uint4*)(g_w3h + c * 8192);
        const uint4* awl = (const uint4*)(g_w3l + c * 8192);
        for (int i = t; i < 1024; i += 256) {
            int oc = i >> 3, seg = i & 7;
            *(uint4*)(Ah + oc * A_STR + seg * 8) = awh[i];
            *(uint4*)(Al + oc * A_STR + seg * 8) = awl[i];
        }
        // B chunk copy: [56 n][64 k] hi/lo (rows 49..55 zero), 448 uint4 each
        for (int i = t; i < 448; i += 256) {
            int n = i >> 3, seg = i & 7;
            uint4 vh = make_uint4(0u, 0u, 0u, 0u), vl = vh;
            if (n < 49) {
                int prow = n / 7, pcol = n - prow * 7;
                int srcrow = (2 * prow + ky) * 15 + 2 * pcol + kx;
                vh = ((const uint4*)(Xh + srcrow * 64))[seg];
                vl = ((const uint4*)(Xl + srcrow * 64))[seg];
            }
            *(uint4*)(Bh + n * A_STR + seg * 8) = vh;
            *(uint4*)(Bl + n * A_STR + seg * 8) = vl;
        }
        __syncthreads();
#pragma unroll
        for (int ks = 0; ks < 4; ks++) {
            int k0 = ks * 16;
            int row0 = wid * 16 + r;
            unsigned ah0 = *(const unsigned*)(Ah + row0 * A_STR + k0 + cp);
            unsigned ah1 = *(const unsigned*)(Ah + (row0 + 8) * A_STR + k0 + cp);
            unsigned ah2 = *(const unsigned*)(Ah + row0 * A_STR + k0 + 8 + cp);
            unsigned ah3 = *(const unsigned*)(Ah + (row0 + 8) * A_STR + k0 + 8 + cp);
            unsigned al0 = *(const unsigned*)(Al + row0 * A_STR + k0 + cp);
            unsigned al1 = *(const unsigned*)(Al + (row0 + 8) * A_STR + k0 + cp);
            unsigned al2 = *(const unsigned*)(Al + row0 * A_STR + k0 + 8 + cp);
            unsigned al3 = *(const unsigned*)(Al + (row0 + 8) * A_STR + k0 + 8 + cp);
#pragma unroll
            for (int nt = 0; nt < 7; nt++) {
                int n = nt * 8 + r;
                unsigned bh0 = *(const unsigned*)(Bh + n * A_STR + k0 + cp);
                unsigned bh1 = *(const unsigned*)(Bh + n * A_STR + k0 + 8 + cp);
                unsigned bl0 = *(const unsigned*)(Bl + n * A_STR + k0 + cp);
                unsigned bl1 = *(const unsigned*)(Bl + n * A_STR + k0 + 8 + cp);
                mma16816(facc[nt], ah0, ah1, ah2, ah3, bh0, bh1);
                mma16816(facc[nt], ah0, ah1, ah2, ah3, bl0, bl1);
                mma16816(facc[nt], al0, al1, al2, al3, bh0, bh1);
            }
        }
    }
    // epilogue: bias + leaky + store to g_feat [oc][49]
    float* o = g_feat + (size_t)b * 6272;
    int oc0 = wid * 16 + r;
    float bv0 = __ldg(&bias[oc0]);
    float bv8 = __ldg(&bias[oc0 + 8]);
#pragma unroll
    for (int nt = 0; nt < 7; nt++) {
        int px = nt * 8 + cp;
        if (px < 49) {
            o[oc0 * 49 + px] = leaky(facc[nt][0] + bv0);
            o[(oc0 + 8) * 49 + px] = leaky(facc[nt][2] + bv8);
        }
        if (px + 1 < 49) {
            o[oc0 * 49 + px + 1] = leaky(facc[nt][1] + bv0);
            o[(oc0 + 8) * 49 + px + 1] = leaky(facc[nt][3] + bv8);
        }
    }
}

// ---------------- fused dual-head GEMM (split-K, 8x4 reg tiles) -------------
__global__ void __launch_bounds__(256) k_gemm(
    const float* __restrict__ Ac, const float* __restrict__ Ar,
    const float* __restrict__ Bc, const float* __restrict__ Br,
    float* __restrict__ part, int K, int Ksplit) {
    __shared__ float sA[16 * 128];        // [k][m]
    __shared__ float sB[16 * 64];         // [k][n]
    int head = blockIdx.y >> 2;
    int m0 = blockIdx.x * 128, n0 = (blockIdx.y & 3) * 64;
    int k0 = blockIdx.z * Ksplit;
    const float* A  = head ? Ar : Ac;
    const float* Bw = head ? Br : Bc;
    int t = threadIdx.x;                  // 256
    int a_m = t >> 1, a_f = (t & 1) * 2;            // 2 float4 per thread (A)
    int b_n = t >> 2, b_f = t & 3;                  // 1 float4 per thread (B)
    const float* Ap = A + (size_t)(m0 + a_m) * K + k0;
    const float* Bp = Bw + (size_t)(n0 + b_n) * K + k0;
    int tm = t >> 4, tn = t & 15;
    float acc[32];
#pragma unroll
    for (int i = 0; i < 32; i++) acc[i] = 0.f;
    for (int kk = 0; kk < Ksplit; kk += 16) {
        float4 av0 = *(const float4*)(Ap + kk + a_f * 4);
        float4 av1 = *(const float4*)(Ap + kk + a_f * 4 + 4);
        float4 bv  = *(const float4*)(Bp + kk + b_f * 4);
        __syncthreads();
        sA[(a_f * 4 + 0) * 128 + a_m] = av0.x;
        sA[(a_f * 4 + 1) * 128 + a_m] = av0.y;
        sA[(a_f * 4 + 2) * 128 + a_m] = av0.z;
        sA[(a_f * 4 + 3) * 128 + a_m] = av0.w;
        sA[(a_f * 4 + 4) * 128 + a_m] = av1.x;
        sA[(a_f * 4 + 5) * 128 + a_m] = av1.y;
        sA[(a_f * 4 + 6) * 128 + a_m] = av1.z;
        sA[(a_f * 4 + 7) * 128 + a_m] = av1.w;
        sB[(b_f * 4 + 0) * 64 + b_n] = bv.x;
        sB[(b_f * 4 + 1) * 64 + b_n] = bv.y;
        sB[(b_f * 4 + 2) * 64 + b_n] = bv.z;
        sB[(b_f * 4 + 3) * 64 + b_n] = bv.w;
        __syncthreads();
#pragma unroll
        for (int k = 0; k < 16; k++) {
            float4 a0 = *(const float4*)&sA[k * 128 + tm * 8];
            float4 a1 = *(const float4*)&sA[k * 128 + tm * 8 + 4];
            float4 bq = *(const float4*)&sB[k * 64 + tn * 4];
            float a_[8] = {a0.x, a0.y, a0.z, a0.w, a1.x, a1.y, a1.z, a1.w};
#pragma unroll
            for (int i = 0; i < 8; i++) {
                acc[i * 4 + 0] = fmaf(a_[i], bq.x, acc[i * 4 + 0]);
                acc[i * 4 + 1] = fmaf(a_[i], bq.y, acc[i * 4 + 1]);
                acc[i * 4 + 2] = fmaf(a_[i], bq.z, acc[i * 4 + 2]);
                acc[i * 4 + 3] = fmaf(a_[i], bq.w, acc[i * 4 + 3]);
            }
        }
    }
    float* p = part + (size_t)(blockIdx.z * 2 + head) * (512 * 256);
#pragma unroll
    for (int i = 0; i < 8; i++) {
        float4* rowp = (float4*)(p + (size_t)(m0 + tm * 8 + i) * 256 + n0 + tn * 4);
        *rowp = make_float4(acc[i * 4], acc[i * 4 + 1], acc[i * 4 + 2], acc[i * 4 + 3]);
    }
}

// ---------------- split-K reduce + bias + relu (both heads) -----------------
__global__ void k_reduce(const float* __restrict__ part,
                         const float* __restrict__ cb, const float* __restrict__ rb,
                         float* __restrict__ out, int S) {
    int i = blockIdx.x * 256 + threadIdx.x;        // over 2*512*256
    int head = i >> 17;
    int j = i & 131071;
    float v = 0.f;
    for (int s = 0; s < S; s++) v += part[(size_t)(s * 2 + head) * 131072 + j];
    v += (head ? rb : cb)[j & 255];
    out[i] = fmaxf(v, 0.f);
}

// ---------------- final heads ----------------------------------------------
__global__ void k_fc3(const float* __restrict__ cw, const float* __restrict__ cb,
                      const float* __restrict__ rw, const float* __restrict__ rb,
                      float* __restrict__ out) {
    __shared__ float hc[256], hr[256];
    int b = blockIdx.x, t = threadIdx.x;           // 64 threads
    for (int i = t; i < 256; i += 64) {
        hc[i] = g_h2[b * 256 + i];
        hr[i] = g_h2[131072 + b * 256 + i];
    }
    __syncthreads();
    if (t >= 47) return;
    const float* w = (t == 0) ? cw : rw + (t - 1) * 256;
    const float* h = (t == 0) ? hc : hr;
    float acc = (t == 0) ? cb[0] : rb[t - 1];
    for (int k = 0; k < 256; k++) acc = fmaf(h[k], w[k], acc);
    if (t == 0) out[b] = acc;
    else        out[512 + b * 46 + (t - 1)] = acc;
}

// ---------------- launch ----------------------------------------------------
extern "C" void kernel_launch(void* const* d_in, const int* in_sizes, int n_in,
                              void* d_out, int out_size) {
    const float* pts = (const float*)d_in[0];
    const float* rot = (const float*)d_in[1];
    const float* w1  = (const float*)d_in[2];  const float* b1  = (const float*)d_in[3];
    const float* w2  = (const float*)d_in[4];  const float* b2  = (const float*)d_in[5];
    const float* w3  = (const float*)d_in[6];  const float* b3  = (const float*)d_in[7];
    const float* cw1 = (const float*)d_in[8];  const float* cb1 = (const float*)d_in[9];
    const float* cw2 = (const float*)d_in[10]; const float* cb2 = (const float*)d_in[11];
    const float* cw3 = (const float*)d_in[12]; const float* cb3 = (const float*)d_in[13];
    const float* rw1 = (const float*)d_in[14]; const float* rb1 = (const float*)d_in[15];
    const float* rw2 = (const float*)d_in[16]; const float* rb2 = (const float*)d_in[17];
    const float* rw3 = (const float*)d_in[18]; const float* rb3 = (const float*)d_in[19];
    float* out = (float*)d_out;

    float *featp, *h1p, *h2p, *partp;
    cudaGetSymbolAddress((void**)&featp, g_feat);
    cudaGetSymbolAddress((void**)&h1p, g_h1);
    cudaGetSymbolAddress((void**)&h2p, g_h2);
    cudaGetSymbolAddress((void**)&partp, g_part);

    const int SM1 = (49152 + 3456 + 1536 + 128) * 4;   // 217,088 B
    const int SM2 = (9920 + 2304) * 4;                 // 48,896 B
    const int SM3 = 26496 * 2;                         // 52,992 B (bf16 units)
    cudaFuncSetAttribute(k_fuse1, cudaFuncAttributeMaxDynamicSharedMemorySize, SM1);
    cudaFuncSetAttribute(k_conv2, cudaFuncAttributeMaxDynamicSharedMemorySize, SM2);
    cudaFuncSetAttribute(k_conv3_mma, cudaFuncAttributeMaxDynamicSharedMemorySize, SM3);

    k_prep<<<(3456 + 18432 + 73728 + 255) / 256, 256>>>(w1, w2, w3);
    k_fuse1<<<BATCH, 512, SM1>>>(pts, rot, b1);
    k_conv2<<<dim3(BATCH, 2), 256, SM2>>>(b2);
    k_conv3_mma<<<BATCH, 256, SM3>>>(b3);
    k_gemm<<<dim3(4, 8, 14), 256>>>(featp, featp, cw1, rw1, partp, 6272, 448);
    k_reduce<<<1024, 256>>>(partp, cb1, rb1, h1p, 14);
    k_gemm<<<dim3(4, 8, 2), 256>>>(h1p, h1p + 131072, cw2, rw2, partp, 256, 128);
    k_reduce<<<1024, 256>>>(partp, cb2, rb2, h2p, 2);
    k_fc3<<<BATCH, 64>>>(cw3, cb3, rw3, rb3, out);
    (void)in_sizes; (void)n_in; (void)out_size;
}

// round 16
// speedup vs baseline: 2.8136x; 1.0896x over previous
#include <cuda_runtime.h>
#include <cuda_bf16.h>

#define BATCH 512
#define NPTS  512
#define NROT  12
#define IMG   64

// padded strides (bank-conflict-free for stride-2 quad reads)
#define C1_ROW 40
#define C1_IC  1240               // 31 * 40

// ---------------- scratch (device globals; no allocations allowed) ----------
__device__ float g_c1[BATCH * 32 * C1_IC];            // 81 MB
// conv2 output: bf16 hi/lo, channels-last [b][pix(225)][64]
__device__ __align__(16) __nv_bfloat16 g_c2h[BATCH * 225 * 64];
__device__ __align__(16) __nv_bfloat16 g_c2l[BATCH * 225 * 64];
// conv3 output (= FC input) bf16 hi/lo [b][6272]
__device__ __align__(16) __nv_bfloat16 g_fh[BATCH * 6272];
__device__ __align__(16) __nv_bfloat16 g_fl[BATCH * 6272];
__device__ float g_h1[2 * BATCH * 256];
__device__ float g_h2[2 * BATCH * 256];
__device__ float g_part[28 * BATCH * 256];            // [split*2+head][b][n]
__device__ float g_wt1[108 * 32];                     // [r][oc]
__device__ float g_wt2[288 * 64];                     // [r][oc]
// conv3 weights bf16 hi/lo, [tap(9)][oc(128)][ic(64)]
__device__ __align__(16) __nv_bfloat16 g_w3h[9 * 128 * 64];
__device__ __align__(16) __nv_bfloat16 g_w3l[9 * 128 * 64];
// FC1 weights bf16 hi/lo, [n(256)][k(6272)] per head
__device__ __align__(16) __nv_bfloat16 g_wc1h[256 * 6272];
__device__ __align__(16) __nv_bfloat16 g_wc1l[256 * 6272];
__device__ __align__(16) __nv_bfloat16 g_wr1h[256 * 6272];
__device__ __align__(16) __nv_bfloat16 g_wr1l[256 * 6272];

__device__ __forceinline__ float leaky(float v) {
    return v >= 0.f ? v : 0.2f * v;
}

// 8 oc x 4 px outer-product FMA block
__device__ __forceinline__ void fma8x4(float* acc, float v0, float v1,
                                       float v2, float v3,
                                       float4 w0, float4 w1) {
    float w[8] = {w0.x, w0.y, w0.z, w0.w, w1.x, w1.y, w1.z, w1.w};
#pragma unroll
    for (int j = 0; j < 8; j++) {
        acc[j * 4 + 0] = fmaf(v0, w[j], acc[j * 4 + 0]);
        acc[j * 4 + 1] = fmaf(v1, w[j], acc[j * 4 + 1]);
        acc[j * 4 + 2] = fmaf(v2, w[j], acc[j * 4 + 2]);
        acc[j * 4 + 3] = fmaf(v3, w[j], acc[j * 4 + 3]);
    }
}

// bf16 m16n8k16 warp MMA (baseline PTX, legal on sm_100)
__device__ __forceinline__ void mma16816(float* d,
                                         unsigned a0, unsigned a1,
                                         unsigned a2, unsigned a3,
                                         unsigned b0, unsigned b1) {
    asm volatile(
        "mma.sync.aligned.m16n8k16.row.col.f32.bf16.bf16.f32 "
        "{%0,%1,%2,%3}, {%4,%5,%6,%7}, {%8,%9}, {%0,%1,%2,%3};"
        : "+f"(d[0]), "+f"(d[1]), "+f"(d[2]), "+f"(d[3])
        : "r"(a0), "r"(a1), "r"(a2), "r"(a3), "r"(b0), "r"(b1));
}

__device__ __forceinline__ void bf_split(float v, __nv_bfloat16& h, __nv_bfloat16& l) {
    h = __float2bfloat16(v);
    l = __float2bfloat16(v - __bfloat162float(h));
}

// ---------------- weight prep --------------------------------------------
__global__ void k_prep(const float* __restrict__ w1, const float* __restrict__ w2,
                       const float* __restrict__ w3, const float* __restrict__ cw1,
                       const float* __restrict__ rw1) {
    int i = blockIdx.x * 256 + threadIdx.x;
    if (i < 3456) {
        int r = i >> 5, oc = i & 31;
        g_wt1[i] = w1[oc * 108 + r];
        return;
    }
    i -= 3456;
    if (i < 18432) {
        int r = i >> 6, oc = i & 63;
        g_wt2[i] = w2[oc * 288 + r];
        return;
    }
    i -= 18432;
    if (i < 73728) {
        // dst [tap][oc][ic]; src w3[oc][ic*9 + tap]
        int c = i >> 13, e = i & 8191;
        int oc = e >> 6, ic = e & 63;
        bf_split(w3[oc * 576 + ic * 9 + c], g_w3h[i], g_w3l[i]);
        return;
    }
    i -= 73728;
    if (i < 1605632) {
        bf_split(cw1[i], g_wc1h[i], g_wc1l[i]);
        return;
    }
    i -= 1605632;
    if (i < 1605632) {
        bf_split(rw1[i], g_wr1h[i], g_wr1l[i]);
    }
}

// ---------------- fused scatter + conv1 (per-batch block) -------------------
__global__ void __launch_bounds__(512, 1) k_fuse1(
    const float* __restrict__ pts, const float* __restrict__ rot,
    const float* __restrict__ bias) {
    extern __shared__ float sm[];
    float* s_img = sm;                    // 49152 floats (12 x 64 x 64 deint-x)
    float* s_w   = sm + 49152;            // 3456
    float* s_pts = s_w + 3456;            // 1536
    float* s_rot = s_pts + 1536;          // 108
    unsigned int* u_img = (unsigned int*)s_img;
    int b = blockIdx.x, t = threadIdx.x;

    for (int i = t; i < 49152 / 4; i += 512)
        ((uint4*)u_img)[i] = make_uint4(0u, 0u, 0u, 0u);
    for (int i = t; i < 1536; i += 512) s_pts[i] = pts[b * 1536 + i];
    if (t < 108) s_rot[t] = rot[t];
    for (int i = t; i < 3456 / 4; i += 512)
        ((float4*)s_w)[i] = ((const float4*)g_wt1)[i];
    __syncthreads();

    // scatter: key = (n<<23) | (valbits>>9); atomicMax => last point index wins
    for (int task = t; task < NROT * NPTS; task += 512) {
        int m = task >> 9, n = task & 511;
        float x = s_pts[n * 3], y = s_pts[n * 3 + 1], z = s_pts[n * 3 + 2];
        const float* r = s_rot + m * 9;
        float xr = r[0] * x + r[1] * y + r[2] * z;
        float zr = r[6] * x + r[7] * y + r[8] * z;
        float fx = rintf((xr + 2.0f) / 0.0625f);   // round-half-even == jnp.round
        float fy = rintf((y + 2.0f) / 0.0625f);
        int px = (int)fx, py = (int)fy;
        bool ok = (px >= 0) && (px < IMG) && (py >= 0) && (py < IMG);
        if (!ok) { px = 0; py = 0; }               // proj*ok -> OOB hits (0,0)
        float val = zr / 10.0f;
        unsigned int key = ((unsigned int)n << 23) | (__float_as_uint(val) >> 9);
        int didx = ((px & 1) << 5) + (px >> 1);    // deinterleave x
        atomicMax(&u_img[(m << 12) + (py << 6) + didx], key);
    }
    __syncthreads();
    for (int i = t; i < 49152 / 4; i += 512) {
        uint4 v = ((uint4*)u_img)[i];
        v.x = (v.x & 0x7fffffu) << 9; v.y = (v.y & 0x7fffffu) << 9;
        v.z = (v.z & 0x7fffffu) << 9; v.w = (v.w & 0x7fffffu) << 9;
        ((uint4*)u_img)[i] = v;                    // decode to float bits
    }
    __syncthreads();

    // conv1: 12ch 64x64 -> 32ch 31x31 stride-2 leaky.
    int pxg = t & 255;
    int row = pxg >> 3, q = pxg & 7;
    bool active = pxg < 248;                        // 31 rows x 8 quads
#pragma unroll
    for (int uu = 0; uu < 2; uu++) {
        int ocg = (t >> 8) + 2 * uu;                // 0..3
        int oc0 = ocg << 3;
        if (active) {
            float acc[32];
#pragma unroll
            for (int j = 0; j < 8; j++) {
                float bv = __ldg(&bias[oc0 + j]);
                acc[j * 4] = bv; acc[j * 4 + 1] = bv;
                acc[j * 4 + 2] = bv; acc[j * 4 + 3] = bv;
            }
            for (int ic = 0; ic < NROT; ic++) {
#pragma unroll
                for (int ky = 0; ky < 3; ky++) {
                    const float* base = s_img + (ic << 12) + ((2 * row + ky) << 6);
                    float4 ef = *(const float4*)(base + 4 * q);
                    float4 of = *(const float4*)(base + 32 + 4 * q);
                    float  e4 = base[4 * q + 4];
                    int r0 = (ic * 9 + ky * 3) << 5;
                    const float4* wp0 = (const float4*)(s_w + r0 + oc0);
                    const float4* wp1 = (const float4*)(s_w + r0 + 32 + oc0);
                    const float4* wp2 = (const float4*)(s_w + r0 + 64 + oc0);
                    fma8x4(acc, ef.x, ef.y, ef.z, ef.w, wp0[0], wp0[1]);
                    fma8x4(acc, of.x, of.y, of.z, of.w, wp1[0], wp1[1]);
                    fma8x4(acc, ef.y, ef.z, ef.w, e4,   wp2[0], wp2[1]);
                }
            }
#pragma unroll
            for (int j = 0; j < 8; j++) {
                float* o = g_c1 + ((size_t)b * 32 + oc0 + j) * C1_IC + row * C1_ROW;
#pragma unroll
                for (int l = 0; l < 4; l++) {
                    int px = 4 * q + l;
                    if (px < 31)
                        o[((px & 1) << 4) + (px >> 1)] = leaky(acc[j * 4 + l]);
                }
            }
        }
    }
}

// ---------------- conv2: 32ch 31x31 -> 64ch 15x15 ---------------------------
// output: bf16 hi/lo channels-last [b][pix][64]
__global__ void __launch_bounds__(256, 3) k_conv2(const float* __restrict__ bias) {
    extern __shared__ float sm[];
    float* s_in = sm;                     // 8 * 1240 = 9920 fl
    float* s_w  = sm + 9920;              // 8*9*32 = 2304 fl
    int b = blockIdx.x, half = blockIdx.y, t = threadIdx.x;

    int ocg = t >> 6;                     // 4 groups of 8 oc
    int ocl = ocg << 3;                   // local oc in half
    int oc0 = half * 32 + ocl;
    int pxg = t & 63;                     // 15 rows x 4 quads = 60 active
    int row = pxg >> 2, q = pxg & 3;
    bool active = pxg < 60;
    float acc[32];
#pragma unroll
    for (int j = 0; j < 8; j++) {
        float bv = __ldg(&bias[oc0 + j]);
        acc[j * 4] = bv; acc[j * 4 + 1] = bv;
        acc[j * 4 + 2] = bv; acc[j * 4 + 3] = bv;
    }
    for (int chunk = 0; chunk < 4; chunk++) {
        __syncthreads();
        const float4* isrc =
            (const float4*)(g_c1 + (size_t)b * (32 * C1_IC) + chunk * 8 * C1_IC);
        for (int i = t; i < 2480; i += 256) ((float4*)s_in)[i] = isrc[i];
        for (int i = t; i < 72 * 8; i += 256) {
            int rr = i >> 3, c4 = i & 7;
            ((float4*)s_w)[rr * 8 + c4] =
                *(const float4*)(g_wt2 + (chunk * 72 + rr) * 64 + half * 32 + c4 * 4);
        }
        __syncthreads();
        if (active) {
            for (int icl = 0; icl < 8; icl++) {
#pragma unroll
                for (int ky = 0; ky < 3; ky++) {
                    const float* base = s_in + icl * C1_IC + (2 * row + ky) * C1_ROW;
                    float4 ef = *(const float4*)(base + 4 * q);
                    float4 of = *(const float4*)(base + 16 + 4 * q);
                    float  e4 = base[4 * q + 4];
                    int r0 = (icl * 9 + ky * 3) << 5;
                    const float4* wp0 = (const float4*)(s_w + r0 + ocl);
                    const float4* wp1 = (const float4*)(s_w + r0 + 32 + ocl);
                    const float4* wp2 = (const float4*)(s_w + r0 + 64 + ocl);
                    fma8x4(acc, ef.x, ef.y, ef.z, ef.w, wp0[0], wp0[1]);
                    fma8x4(acc, of.x, of.y, of.z, of.w, wp1[0], wp1[1]);
                    fma8x4(acc, ef.y, ef.z, ef.w, e4,   wp2[0], wp2[1]);
                }
            }
        }
    }
    if (active) {
#pragma unroll
        for (int l = 0; l < 4; l++) {
            int px = 4 * q + l;
            if (px < 15) {
                size_t base = ((size_t)b * 225 + row * 15 + px) * 64 + oc0;
#pragma unroll
                for (int j = 0; j < 8; j++) {
                    float v = leaky(acc[j * 4 + l]);
                    bf_split(v, g_c2h[base + j], g_c2l[base + j]);
                }
            }
        }
    }
}

// ---------------- conv3 via mma.sync bf16 hi/lo ------------------------------
// Per batch: D[128 oc, 56 px(pad)] = W[128,576] * im2col[576,56]
// K-chunk = one (ky,kx) tap = 64 contiguous channels (channels-last input).
// smem (bf16): Ah[128*72]@0, Al@9216, Bh[56*72]@18432, Bl@22464 -> 52992 B.
#define A_STR 72
__global__ void __launch_bounds__(256) k_conv3_mma(const float* __restrict__ bias) {
    extern __shared__ __nv_bfloat16 smb[];
    __nv_bfloat16* Ah = smb;
    __nv_bfloat16* Al = smb + 9216;
    __nv_bfloat16* Bh = smb + 18432;
    __nv_bfloat16* Bl = smb + 22464;
    int b = blockIdx.x, t = threadIdx.x;
    int wid = t >> 5, lane = t & 31;
    int r = lane >> 2, cp = (lane & 3) * 2;

    const __nv_bfloat16* Xh = g_c2h + (size_t)b * (225 * 64);
    const __nv_bfloat16* Xl = g_c2l + (size_t)b * (225 * 64);
    float facc[7][4];
#pragma unroll
    for (int nt = 0; nt < 7; nt++)
#pragma unroll
        for (int j = 0; j < 4; j++) facc[nt][j] = 0.f;

    for (int c = 0; c < 9; c++) {
        int ky = c / 3, kx = c - 3 * (c / 3);
        __syncthreads();
        // A chunk copy: [128 oc][64 k] hi/lo, 1024 uint4 each
        const uint4* awh = (const uint4*)(g_w3h + c * 8192);
        const uint4* awl = (const uint4*)(g_w3l + c * 8192);
        for (int i = t; i < 1024; i += 256) {
            int oc = i >> 3, seg = i & 7;
            *(uint4*)(Ah + oc * A_STR + seg * 8) = awh[i];
            *(uint4*)(Al + oc * A_STR + seg * 8) = awl[i];
        }
        // B chunk copy: [56 n][64 k] hi/lo (rows 49..55 zero), 448 uint4 each
        for (int i = t; i < 448; i += 256) {
            int n = i >> 3, seg = i & 7;
            uint4 vh = make_uint4(0u, 0u, 0u, 0u), vl = vh;
            if (n < 49) {
                int prow = n / 7, pcol = n - prow * 7;
                int srcrow = (2 * prow + ky) * 15 + 2 * pcol + kx;
                vh = ((const uint4*)(Xh + srcrow * 64))[seg];
                vl = ((const uint4*)(Xl + srcrow * 64))[seg];
            }
            *(uint4*)(Bh + n * A_STR + seg * 8) = vh;
            *(uint4*)(Bl + n * A_STR + seg * 8) = vl;
        }
        __syncthreads();
#pragma unroll
        for (int ks = 0; ks < 4; ks++) {
            int k0 = ks * 16;
            int row0 = wid * 16 + r;
            unsigned ah0 = *(const unsigned*)(Ah + row0 * A_STR + k0 + cp);
            unsigned ah1 = *(const unsigned*)(Ah + (row0 + 8) * A_STR + k0 + cp);
            unsigned ah2 = *(const unsigned*)(Ah + row0 * A_STR + k0 + 8 + cp);
            unsigned ah3 = *(const unsigned*)(Ah + (row0 + 8) * A_STR + k0 + 8 + cp);
            unsigned al0 = *(const unsigned*)(Al + row0 * A_STR + k0 + cp);
            unsigned al1 = *(const unsigned*)(Al + (row0 + 8) * A_STR + k0 + cp);
            unsigned al2 = *(const unsigned*)(Al + row0 * A_STR + k0 + 8 + cp);
            unsigned al3 = *(const unsigned*)(Al + (row0 + 8) * A_STR + k0 + 8 + cp);
#pragma unroll
            for (int nt = 0; nt < 7; nt++) {
                int n = nt * 8 + r;
                unsigned bh0 = *(const unsigned*)(Bh + n * A_STR + k0 + cp);
                unsigned bh1 = *(const unsigned*)(Bh + n * A_STR + k0 + 8 + cp);
                unsigned bl0 = *(const unsigned*)(Bl + n * A_STR + k0 + cp);
                unsigned bl1 = *(const unsigned*)(Bl + n * A_STR + k0 + 8 + cp);
                mma16816(facc[nt], ah0, ah1, ah2, ah3, bh0, bh1);
                mma16816(facc[nt], ah0, ah1, ah2, ah3, bl0, bl1);
                mma16816(facc[nt], al0, al1, al2, al3, bh0, bh1);
            }
        }
    }
    // epilogue: bias + leaky + bf16 hi/lo split -> g_fh/g_fl [b][oc*49+px]
    __nv_bfloat16* oh = g_fh + (size_t)b * 6272;
    __nv_bfloat16* ol = g_fl + (size_t)b * 6272;
    int oc0 = wid * 16 + r;
    float bv0 = __ldg(&bias[oc0]);
    float bv8 = __ldg(&bias[oc0 + 8]);
#pragma unroll
    for (int nt = 0; nt < 7; nt++) {
        int px = nt * 8 + cp;
        if (px < 49) {
            bf_split(leaky(facc[nt][0] + bv0), oh[oc0 * 49 + px], ol[oc0 * 49 + px]);
            bf_split(leaky(facc[nt][2] + bv8), oh[(oc0 + 8) * 49 + px], ol[(oc0 + 8) * 49 + px]);
        }
        if (px + 1 < 49) {
            bf_split(leaky(facc[nt][1] + bv0), oh[oc0 * 49 + px + 1], ol[oc0 * 49 + px + 1]);
            bf_split(leaky(facc[nt][3] + bv8), oh[(oc0 + 8) * 49 + px + 1], ol[(oc0 + 8) * 49 + px + 1]);
        }
    }
}

// ---------------- FC1 dual-head GEMM via mma.sync bf16 hi/lo -----------------
// C[head][512,256] = feat[512,6272] * W[head][256,6272]^T, split-K=7.
// grid: x = m-tile(8 of 64), y = n-tile(4 of 64) + head*4, z = splitK(7).
// smem (bf16): Ah[64*72]@0, Al@4608, Bh@9216, Bl@13824 -> 36864 B.
__global__ void __launch_bounds__(256) k_fc1_mma(float* __restrict__ part) {
    extern __shared__ __nv_bfloat16 smb[];
    __nv_bfloat16* Ah = smb;
    __nv_bfloat16* Al = smb + 4608;
    __nv_bfloat16* Bh = smb + 9216;
    __nv_bfloat16* Bl = smb + 13824;
    int t = threadIdx.x;
    int wid = t >> 5, lane = t & 31;
    int r = lane >> 2, cp = (lane & 3) * 2;
    int mw = wid & 3, nw = wid >> 2;              // 4 m-warps x 2 n-halves
    int head = blockIdx.y >> 2;
    int m0 = blockIdx.x * 64, n0 = (blockIdx.y & 3) * 64;
    int k0 = blockIdx.z * 896;
    const __nv_bfloat16* Agh = g_fh;
    const __nv_bfloat16* Agl = g_fl;
    const __nv_bfloat16* Bgh = head ? g_wr1h : g_wc1h;
    const __nv_bfloat16* Bgl = head ? g_wr1l : g_wc1l;

    float facc[4][4];
#pragma unroll
    for (int nt = 0; nt < 4; nt++)
#pragma unroll
        for (int j = 0; j < 4; j++) facc[nt][j] = 0.f;

    for (int c = 0; c < 14; c++) {
        __syncthreads();
        int kc = k0 + c * 64;
        for (int i = t; i < 512; i += 256) {
            int row = i >> 3, seg = i & 7;
            size_t as = (size_t)(m0 + row) * 6272 + kc + seg * 8;
            size_t bs = (size_t)(n0 + row) * 6272 + kc + seg * 8;
            *(uint4*)(Ah + row * A_STR + seg * 8) = *(const uint4*)(Agh + as);
            *(uint4*)(Al + row * A_STR + seg * 8) = *(const uint4*)(Agl + as);
            *(uint4*)(Bh + row * A_STR + seg * 8) = *(const uint4*)(Bgh + bs);
            *(uint4*)(Bl + row * A_STR + seg * 8) = *(const uint4*)(Bgl + bs);
        }
        __syncthreads();
#pragma unroll
        for (int ks = 0; ks < 4; ks++) {
            int kk = ks * 16;
            int row0 = mw * 16 + r;
            unsigned ah0 = *(const unsigned*)(Ah + row0 * A_STR + kk + cp);
            unsigned ah1 = *(const unsigned*)(Ah + (row0 + 8) * A_STR + kk + cp);
            unsigned ah2 = *(const unsigned*)(Ah + row0 * A_STR + kk + 8 + cp);
            unsigned ah3 = *(const unsigned*)(Ah + (row0 + 8) * A_STR + kk + 8 + cp);
            unsigned al0 = *(const unsigned*)(Al + row0 * A_STR + kk + cp);
            unsigned al1 = *(const unsigned*)(Al + (row0 + 8) * A_STR + kk + cp);
            unsigned al2 = *(const unsigned*)(Al + row0 * A_STR + kk + 8 + cp);
            unsigned al3 = *(const unsigned*)(Al + (row0 + 8) * A_STR + kk + 8 + cp);
#pragma unroll
            for (int nt = 0; nt < 4; nt++) {
                int n = nw * 32 + nt * 8 + r;
                unsigned bh0 = *(const unsigned*)(Bh + n * A_STR + kk + cp);
                unsigned bh1 = *(const unsigned*)(Bh + n * A_STR + kk + 8 + cp);
                unsigned bl0 = *(const unsigned*)(Bl + n * A_STR + kk + cp);
                unsigned bl1 = *(const unsigned*)(Bl + n * A_STR + kk + 8 + cp);
                mma16816(facc[nt], ah0, ah1, ah2, ah3, bh0, bh1);
                mma16816(facc[nt], ah0, ah1, ah2, ah3, bl0, bl1);
                mma16816(facc[nt], al0, al1, al2, al3, bh0, bh1);
            }
        }
    }
    float* p = part + (size_t)(blockIdx.z * 2 + head) * 131072;
    int row0 = m0 + mw * 16 + r;
#pragma unroll
    for (int nt = 0; nt < 4; nt++) {
        int col = n0 + nw * 32 + nt * 8 + cp;
        p[row0 * 256 + col]           = facc[nt][0];
        p[row0 * 256 + col + 1]       = facc[nt][1];
        p[(row0 + 8) * 256 + col]     = facc[nt][2];
        p[(row0 + 8) * 256 + col + 1] = facc[nt][3];
    }
}

// ---------------- FFMA GEMM (FC2 only) --------------------------------------
__global__ void __launch_bounds__(256) k_gemm(
    const float* __restrict__ Ac, const float* __restrict__ Ar,
    const float* __restrict__ Bc, const float* __restrict__ Br,
    float* __restrict__ part, int K, int Ksplit) {
    __shared__ float sA[16 * 128];        // [k][m]
    __shared__ float sB[16 * 64];         // [k][n]
    int head = blockIdx.y >> 2;
    int m0 = blockIdx.x * 128, n0 = (blockIdx.y & 3) * 64;
    int k0 = blockIdx.z * Ksplit;
    const float* A  = head ? Ar : Ac;
    const float* Bw = head ? Br : Bc;
    int t = threadIdx.x;                  // 256
    int a_m = t >> 1, a_f = (t & 1) * 2;            // 2 float4 per thread (A)
    int b_n = t >> 2, b_f = t & 3;                  // 1 float4 per thread (B)
    const float* Ap = A + (size_t)(m0 + a_m) * K + k0;
    const float* Bp = Bw + (size_t)(n0 + b_n) * K + k0;
    int tm = t >> 4, tn = t & 15;
    float acc[32];
#pragma unroll
    for (int i = 0; i < 32; i++) acc[i] = 0.f;
    for (int kk = 0; kk < Ksplit; kk += 16) {
        float4 av0 = *(const float4*)(Ap + kk + a_f * 4);
        float4 av1 = *(const float4*)(Ap + kk + a_f * 4 + 4);
        float4 bv  = *(const float4*)(Bp + kk + b_f * 4);
        __syncthreads();
        sA[(a_f * 4 + 0) * 128 + a_m] = av0.x;
        sA[(a_f * 4 + 1) * 128 + a_m] = av0.y;
        sA[(a_f * 4 + 2) * 128 + a_m] = av0.z;
        sA[(a_f * 4 + 3) * 128 + a_m] = av0.w;
        sA[(a_f * 4 + 4) * 128 + a_m] = av1.x;
        sA[(a_f * 4 + 5) * 128 + a_m] = av1.y;
        sA[(a_f * 4 + 6) * 128 + a_m] = av1.z;
        sA[(a_f * 4 + 7) * 128 + a_m] = av1.w;
        sB[(b_f * 4 + 0) * 64 + b_n] = bv.x;
        sB[(b_f * 4 + 1) * 64 + b_n] = bv.y;
        sB[(b_f * 4 + 2) * 64 + b_n] = bv.z;
        sB[(b_f * 4 + 3) * 64 + b_n] = bv.w;
        __syncthreads();
#pragma unroll
        for (int k = 0; k < 16; k++) {
            float4 a0 = *(const float4*)&sA[k * 128 + tm * 8];
            float4 a1 = *(const float4*)&sA[k * 128 + tm * 8 + 4];
            float4 bq = *(const float4*)&sB[k * 64 + tn * 4];
            float a_[8] = {a0.x, a0.y, a0.z, a0.w, a1.x, a1.y, a1.z, a1.w};
#pragma unroll
            for (int i = 0; i < 8; i++) {
                acc[i * 4 + 0] = fmaf(a_[i], bq.x, acc[i * 4 + 0]);
                acc[i * 4 + 1] = fmaf(a_[i], bq.y, acc[i * 4 + 1]);
                acc[i * 4 + 2] = fmaf(a_[i], bq.z, acc[i * 4 + 2]);
                acc[i * 4 + 3] = fmaf(a_[i], bq.w, acc[i * 4 + 3]);
            }
        }
    }
    float* p = part + (size_t)(blockIdx.z * 2 + head) * (512 * 256);
#pragma unroll
    for (int i = 0; i < 8; i++) {
        float4* rowp = (float4*)(p + (size_t)(m0 + tm * 8 + i) * 256 + n0 + tn * 4);
        *rowp = make_float4(acc[i * 4], acc[i * 4 + 1], acc[i * 4 + 2], acc[i * 4 + 3]);
    }
}

// ---------------- split-K reduce + bias + relu (both heads) -----------------
__global__ void k_reduce(const float* __restrict__ part,
                         const float* __restrict__ cb, const float* __restrict__ rb,
                         float* __restrict__ out, int S) {
    int i = blockIdx.x * 256 + threadIdx.x;        // over 2*512*256
    int head = i >> 17;
    int j = i & 131071;
    float v = 0.f;
    for (int s = 0; s < S; s++) v += part[(size_t)(s * 2 + head) * 131072 + j];
    v += (head ? rb : cb)[j & 255];
    out[i] = fmaxf(v, 0.f);
}

// ---------------- final heads ----------------------------------------------
__global__ void k_fc3(const float* __restrict__ cw, const float* __restrict__ cb,
                      const float* __restrict__ rw, const float* __restrict__ rb,
                      float* __restrict__ out) {
    __shared__ float hc[256], hr[256];
    int b = blockIdx.x, t = threadIdx.x;           // 64 threads
    for (int i = t; i < 256; i += 64) {
        hc[i] = g_h2[b * 256 + i];
        hr[i] = g_h2[131072 + b * 256 + i];
    }
    __syncthreads();
    if (t >= 47) return;
    const float* w = (t == 0) ? cw : rw + (t - 1) * 256;
    const float* h = (t == 0) ? hc : hr;
    float acc = (t == 0) ? cb[0] : rb[t - 1];
    for (int k = 0; k < 256; k++) acc = fmaf(h[k], w[k], acc);
    if (t == 0) out[b] = acc;
    else        out[512 + b * 46 + (t - 1)] = acc;
}

// ---------------- launch ----------------------------------------------------
extern "C" void kernel_launch(void* const* d_in, const int* in_sizes, int n_in,
                              void* d_out, int out_size) {
    const float* pts = (const float*)d_in[0];
    const float* rot = (const float*)d_in[1];
    const float* w1  = (const float*)d_in[2];  const float* b1  = (const float*)d_in[3];
    const float* w2  = (const float*)d_in[4];  const float* b2  = (const float*)d_in[5];
    const float* w3  = (const float*)d_in[6];  const float* b3  = (const float*)d_in[7];
    const float* cw1 = (const float*)d_in[8];  const float* cb1 = (const float*)d_in[9];
    const float* cw2 = (const float*)d_in[10]; const float* cb2 = (const float*)d_in[11];
    const float* cw3 = (const float*)d_in[12]; const float* cb3 = (const float*)d_in[13];
    const float* rw1 = (const float*)d_in[14]; const float* rb1 = (const float*)d_in[15];
    const float* rw2 = (const float*)d_in[16]; const float* rb2 = (const float*)d_in[17];
    const float* rw3 = (const float*)d_in[18]; const float* rb3 = (const float*)d_in[19];
    float* out = (float*)d_out;

    float *h1p, *h2p, *partp;
    cudaGetSymbolAddress((void**)&h1p, g_h1);
    cudaGetSymbolAddress((void**)&h2p, g_h2);
    cudaGetSymbolAddress((void**)&partp, g_part);

    const int SM1 = (49152 + 3456 + 1536 + 128) * 4;   // 217,088 B
    const int SM2 = (9920 + 2304) * 4;                 // 48,896 B
    const int SM3 = 26496 * 2;                         // 52,992 B (bf16 units)
    const int SM4 = 18432 * 2;                         // 36,864 B (fc1 mma)
    cudaFuncSetAttribute(k_fuse1, cudaFuncAttributeMaxDynamicSharedMemorySize, SM1);
    cudaFuncSetAttribute(k_conv2, cudaFuncAttributeMaxDynamicSharedMemorySize, SM2);
    cudaFuncSetAttribute(k_conv3_mma, cudaFuncAttributeMaxDynamicSharedMemorySize, SM3);
    cudaFuncSetAttribute(k_fc1_mma, cudaFuncAttributeMaxDynamicSharedMemorySize, SM4);

    int prep_total = 3456 + 18432 + 73728 + 2 * 1605632;
    k_prep<<<(prep_total + 255) / 256, 256>>>(w1, w2, w3, cw1, rw1);
    k_fuse1<<<BATCH, 512, SM1>>>(pts, rot, b1);
    k_conv2<<<dim3(BATCH, 2), 256, SM2>>>(b2);
    k_conv3_mma<<<BATCH, 256, SM3>>>(b3);
    k_fc1_mma<<<dim3(8, 8, 7), 256, SM4>>>(partp);
    k_reduce<<<1024, 256>>>(partp, cb1, rb1, h1p, 7);
    k_gemm<<<dim3(4, 8, 2), 256>>>(h1p, h1p + 131072, cw2, rw2, partp, 256, 128);
    k_reduce<<<1024, 256>>>(partp, cb2, rb2, h2p, 2);
    k_fc3<<<BATCH, 64>>>(cw3, cb3, rw3, rb3, out);
    (void)in_sizes; (void)n_in; (void)out_size;
}